// round 7
// baseline (speedup 1.0000x reference)
#include <cuda_runtime.h>
#include <cuda_bf16.h>
#include <cstdint>
#include <math.h>

#define Tt 512
#define Bb 64
#define Hh 1024
#define G4 4096
#define K2 2048
#define NBLK 128

// ---------------------------------------------------------------------------
// Device globals. Weight rows UNIT-MAJOR: j = u*4 + g, g in {i,f,c,o}.
// ---------------------------------------------------------------------------
__device__ __nv_bfloat16 g_x_hi[(size_t)Tt * Bb * Hh];
__device__ __nv_bfloat16 g_x_lo[(size_t)Tt * Bb * Hh];
__device__ __nv_bfloat16 g_Wx_hi[(size_t)G4 * Hh];
__device__ __nv_bfloat16 g_Wx_lo[(size_t)G4 * Hh];
__device__ __nv_bfloat16 g_Wh_hi[(size_t)G4 * Hh];
__device__ __nv_bfloat16 g_Wh_lo[(size_t)G4 * Hh];
__device__ float g_bias[G4];
__device__ float g_gx[(size_t)Tt * Bb * G4];
__device__ __nv_bfloat16 g_hb_hi[2][Bb * Hh];
__device__ __nv_bfloat16 g_hb_lo[2][Bb * Hh];
__device__ unsigned int g_ctr;

// ---------------------------------------------------------------------------
// PTX helpers — non-'a' instructions only
// ---------------------------------------------------------------------------
__device__ __forceinline__ uint32_t smem_u32(const void* p) {
    uint32_t a;
    asm("{ .reg .u64 t; cvta.to.shared.u64 t, %1; cvt.u32.u64 %0, t; }" : "=r"(a) : "l"(p));
    return a;
}
__device__ __forceinline__ void cp16(uint32_t dst, const void* src) {
    asm volatile("cp.async.cg.shared.global [%0], [%1], 16;" :: "r"(dst), "l"(src) : "memory");
}
#define CP_COMMIT() asm volatile("cp.async.commit_group;" ::: "memory")
template <int N>
__device__ __forceinline__ void cp_wait() {
    asm volatile("cp.async.wait_group %0;" :: "n"(N) : "memory");
}
__device__ __forceinline__ void mma16816(float* c, const uint32_t* a, const uint32_t* b) {
    asm volatile(
        "mma.sync.aligned.m16n8k16.row.col.f32.bf16.bf16.f32 "
        "{%0,%1,%2,%3}, {%4,%5,%6,%7}, {%8,%9}, {%0,%1,%2,%3};"
        : "+f"(c[0]), "+f"(c[1]), "+f"(c[2]), "+f"(c[3])
        : "r"(a[0]), "r"(a[1]), "r"(a[2]), "r"(a[3]), "r"(b[0]), "r"(b[1]));
}
__device__ __forceinline__ void mma16816b(float* c, const uint32_t* a, uint32_t b0, uint32_t b1) {
    asm volatile(
        "mma.sync.aligned.m16n8k16.row.col.f32.bf16.bf16.f32 "
        "{%0,%1,%2,%3}, {%4,%5,%6,%7}, {%8,%9}, {%0,%1,%2,%3};"
        : "+f"(c[0]), "+f"(c[1]), "+f"(c[2]), "+f"(c[3])
        : "r"(a[0]), "r"(a[1]), "r"(a[2]), "r"(a[3]), "r"(b0), "r"(b1));
}
__device__ __forceinline__ void ldsm_x4(uint32_t* r, uint32_t addr) {
    asm volatile("ldmatrix.sync.aligned.m8n8.x4.shared.b16 {%0,%1,%2,%3}, [%4];"
                 : "=r"(r[0]), "=r"(r[1]), "=r"(r[2]), "=r"(r[3]) : "r"(addr));
}
__device__ __forceinline__ void ldsm_x2(uint32_t* r, uint32_t addr) {
    asm volatile("ldmatrix.sync.aligned.m8n8.x2.shared.b16 {%0,%1}, [%2];"
                 : "=r"(r[0]), "=r"(r[1]) : "r"(addr));
}
__device__ __forceinline__ void nsleep() { asm volatile("nanosleep.u32 40;"); }

__device__ __forceinline__ float sigf(float v) { return 1.0f / (1.0f + __expf(-v)); }
__device__ __forceinline__ float tanhf_fast(float v) {
    float e = __expf(-2.0f * fabsf(v));
    float r = (1.0f - e) / (1.0f + e);
    return (v >= 0.0f) ? r : -r;
}

// ---------------------------------------------------------------------------
// Prep kernels
// ---------------------------------------------------------------------------
__global__ void split_x_kernel(const float* __restrict__ x) {
    size_t total = (size_t)Tt * Bb * Hh;
    size_t stride = (size_t)gridDim.x * blockDim.x;
    for (size_t i = (size_t)blockIdx.x * blockDim.x + threadIdx.x; i < total; i += stride) {
        float v = x[i];
        __nv_bfloat16 hi = __float2bfloat16(v);
        g_x_hi[i] = hi;
        g_x_lo[i] = __float2bfloat16(v - __bfloat162float(hi));
    }
}

__global__ void repack_kernel(const float* __restrict__ Wi, const float* __restrict__ Wf,
                              const float* __restrict__ Wc, const float* __restrict__ Wo,
                              const float* __restrict__ bi, const float* __restrict__ bf,
                              const float* __restrict__ bc, const float* __restrict__ bo) {
    size_t total = (size_t)G4 * K2;
    size_t stride = (size_t)gridDim.x * blockDim.x;
    for (size_t idx = (size_t)blockIdx.x * blockDim.x + threadIdx.x; idx < total; idx += stride) {
        int j = (int)(idx / K2);
        int k = (int)(idx % K2);
        int u = j >> 2, g = j & 3;
        const float* src = (g == 0) ? Wi : (g == 1) ? Wf : (g == 2) ? Wc : Wo;
        float v = src[(size_t)u * K2 + k];
        __nv_bfloat16 hi = __float2bfloat16(v);
        __nv_bfloat16 lo = __float2bfloat16(v - __bfloat162float(hi));
        if (k < Hh) {
            g_Wx_hi[(size_t)j * Hh + k] = hi;
            g_Wx_lo[(size_t)j * Hh + k] = lo;
        } else {
            g_Wh_hi[(size_t)j * Hh + (k - Hh)] = hi;
            g_Wh_lo[(size_t)j * Hh + (k - Hh)] = lo;
        }
    }
    for (int j = blockIdx.x * blockDim.x + threadIdx.x; j < G4; j += (int)stride) {
        int u = j >> 2, g = j & 3;
        const float* sb = (g == 0) ? bi : (g == 1) ? bf : (g == 2) ? bc : bo;
        g_bias[j] = sb[u];
    }
}

__global__ void init_state_kernel() {
    int i = blockIdx.x * blockDim.x + threadIdx.x;
    int stride = gridDim.x * blockDim.x;
    __nv_bfloat16 z = __float2bfloat16(0.0f);
    for (int k = i; k < Bb * Hh; k += stride) {
        g_hb_hi[0][k] = z; g_hb_hi[1][k] = z;
        g_hb_lo[0][k] = z; g_hb_lo[1][k] = z;
    }
    if (i == 0) g_ctr = 0u;
}

// ---------------------------------------------------------------------------
// x-GEMM via mma.sync + ldmatrix: gx = x @ Wx^T + b, bf16 hi/lo 3-product.
// CTA 128x128, 8 warps (2m x 4n), warp tile 64x32. K chunks of 32, 2-buffer,
// 2 CTAs/SM (80KB smem). Tail staging keeps LDGSTS off the critical path.
// ---------------------------------------------------------------------------
#define RS 40                           // row stride in bf16 (80B rows)
#define ARR (128 * RS * 2)              // 10240 B per tile array
#define GX_SMEM (2 * 4 * ARR)           // 81920 B

__global__ __launch_bounds__(256, 2) void gemm_x_mma() {
    extern __shared__ char smem[];
    const uint32_t sbase = smem_u32(smem);
    const int tid = threadIdx.x;
    const int w = tid >> 5;
    const int lane = tid & 31;
    const int g = lane >> 2;
    const int t = lane & 3;
    const int n0 = blockIdx.x * 128;
    const int m0 = blockIdx.y * 128;
    const int wm = (w >> 2) * 64;
    const int wn = (w & 3) * 32;
    const int lrow = (lane & 7) + ((lane >> 3) & 1) * 8;
    const int lcol = (lane >> 4) * 8;

    const __nv_bfloat16* __restrict__ xh = g_x_hi;
    const __nv_bfloat16* __restrict__ xl = g_x_lo;
    const __nv_bfloat16* __restrict__ wh = g_Wx_hi;
    const __nv_bfloat16* __restrict__ wl = g_Wx_lo;

    auto stage = [&](int ch, int b) {
        uint32_t base = sbase + (uint32_t)b * 4 * ARR;
#pragma unroll
        for (int it = 0; it < 2; it++) {
            int idx = it * 256 + tid;      // 0..511
            int r = idx >> 2;              // 0..127
            int s = idx & 3;               // 16B segments (8 bf16)
            uint32_t doff = (uint32_t)(r * RS + s * 8) * 2;
            size_t asrc = (size_t)(m0 + r) * Hh + ch * 32 + s * 8;
            size_t bsrc = (size_t)(n0 + r) * Hh + ch * 32 + s * 8;
            cp16(base + 0 * ARR + doff, xh + asrc);
            cp16(base + 1 * ARR + doff, xl + asrc);
            cp16(base + 2 * ARR + doff, wh + bsrc);
            cp16(base + 3 * ARR + doff, wl + bsrc);
        }
        CP_COMMIT();
    };

    float C[4][4][4];
#pragma unroll
    for (int i = 0; i < 4; i++)
#pragma unroll
        for (int j = 0; j < 4; j++)
#pragma unroll
            for (int q = 0; q < 4; q++) C[i][j][q] = 0.0f;

    const uint32_t a_off = (uint32_t)((wm + lrow) * RS + lcol) * 2;
    const uint32_t b_off = (uint32_t)((wn + lrow) * RS + lcol) * 2;

    stage(0, 0);
    for (int ch = 0; ch < 32; ch++) {
        cp_wait<0>();
        __syncthreads();
        // prefetch next chunk; issue overlaps this chunk's math
        if (ch < 31) stage(ch + 1, (ch + 1) & 1);
        const uint32_t buf = sbase + (uint32_t)(ch & 1) * 4 * ARR;
#pragma unroll
        for (int kk = 0; kk < 32; kk += 16) {
            uint32_t ah[4][4], al[4][4], bh[2][4], bl[2][4];
#pragma unroll
            for (int mt = 0; mt < 4; mt++) {
                ldsm_x4(ah[mt], buf + 0 * ARR + a_off + (uint32_t)(mt * 16 * RS + kk) * 2);
                ldsm_x4(al[mt], buf + 1 * ARR + a_off + (uint32_t)(mt * 16 * RS + kk) * 2);
            }
#pragma unroll
            for (int p = 0; p < 2; p++) {
                ldsm_x4(bh[p], buf + 2 * ARR + b_off + (uint32_t)(p * 16 * RS + kk) * 2);
                ldsm_x4(bl[p], buf + 3 * ARR + b_off + (uint32_t)(p * 16 * RS + kk) * 2);
            }
#pragma unroll
            for (int mt = 0; mt < 4; mt++)
#pragma unroll
                for (int nt = 0; nt < 4; nt++) {
                    int p = nt >> 1, s = nt & 1;
                    mma16816b(C[mt][nt], ah[mt], bh[p][s], bh[p][s + 2]);
                    mma16816b(C[mt][nt], ah[mt], bl[p][s], bl[p][s + 2]);
                    mma16816b(C[mt][nt], al[mt], bh[p][s], bh[p][s + 2]);
                }
        }
        __syncthreads();
    }
#pragma unroll
    for (int mt = 0; mt < 4; mt++) {
        int row = m0 + wm + mt * 16 + g;
#pragma unroll
        for (int nt = 0; nt < 4; nt++) {
            int col = n0 + wn + nt * 8 + 2 * t;
            float2 bv = *reinterpret_cast<const float2*>(g_bias + col);
            float2 o0 = { C[mt][nt][0] + bv.x, C[mt][nt][1] + bv.y };
            float2 o1 = { C[mt][nt][2] + bv.x, C[mt][nt][3] + bv.y };
            *reinterpret_cast<float2*>(g_gx + (size_t)row * G4 + col) = o0;
            *reinterpret_cast<float2*>(g_gx + (size_t)(row + 8) * G4 + col) = o1;
        }
    }
}

// ---------------------------------------------------------------------------
// Persistent recurrent kernel: 128 blocks x 256 threads, all 512 steps.
// SMEM (bytes):
//   WH hi [32][1032]bf16 @ 0        (66048)
//   WH lo                @ 66048    (66048)
//   H ring: 4 bufs x { hi [64][72]bf16 (9216) + lo (9216) } @ 132096 (73728)
//   GXS 2 x [64][36]f32 @ 205824 (18432)  -> total 224256
// ---------------------------------------------------------------------------
#define WH_HI_OFF 0
#define WH_LO_OFF 66048
#define HB_OFF    132096
#define HCH_SZ    18432
#define HLO_SUB   9216
#define GXS_OFF   205824
#define GXS_SZ    9216
#define PERSIST_SMEM 224256

__global__ __launch_bounds__(256, 1) void lstm_persist(float* __restrict__ out) {
    extern __shared__ char smem[];
    const uint32_t sbase = smem_u32(smem);
    const int tid = threadIdx.x;
    const int bu = blockIdx.x;
    const int w = tid >> 5;
    const int lane = tid & 31;
    const int g = lane >> 2;
    const int tq = lane & 3;
    const int wm = (w >> 2) * 32;   // 0 or 32
    const int wn = (w & 3) * 8;     // 0,8,16,24

    // ---- load Wh slice into smem (once) ----
    {
        const __nv_bfloat16* shi = g_Wh_hi + (size_t)bu * 32 * Hh;
        const __nv_bfloat16* slo = g_Wh_lo + (size_t)bu * 32 * Hh;
#pragma unroll
        for (int q = 0; q < 16; q++) {
            int idx = q * 256 + tid;
            int row = idx >> 7;
            int seg = idx & 127;
            uint32_t doff = (uint32_t)(row * 1032 + seg * 8) * 2;
            cp16(sbase + WH_HI_OFF + doff, shi + (size_t)row * Hh + seg * 8);
            cp16(sbase + WH_LO_OFF + doff, slo + (size_t)row * Hh + seg * 8);
        }
        CP_COMMIT();
        cp_wait<0>();
    }
    __syncthreads();

    const int lrow = (lane & 7) + ((lane >> 3) & 1) * 8;
    const int lcol = (lane >> 4) * 8;
    const uint32_t a_lane_off = (uint32_t)((wm + lrow) * 72 + lcol) * 2;
    const uint32_t b_lane_off = (uint32_t)((wn + (lane & 7)) * 1032 + ((lane >> 3) & 1) * 8) * 2;
    const uint32_t b_hi_base = sbase + WH_HI_OFF + b_lane_off;
    const uint32_t b_lo_base = sbase + WH_LO_OFF + b_lane_off;

    const int myMt = tq & 1;
    const int row0 = wm + myMt * 16 + g;
    const int row1 = row0 + 8;
    const int u_glob = bu * 8 + (wn >> 2) + (tq >> 1);

    float creg0 = 0.0f, creg1 = 0.0f;
    float hlast0 = 0.0f, hlast1 = 0.0f;

    // gx prefetch into double-buffered GXS
    auto prefetch_gx = [&](int tt) {
        uint32_t gbase = sbase + GXS_OFF + (uint32_t)(tt & 1) * GXS_SZ;
#pragma unroll
        for (int q = 0; q < 2; q++) {
            int idx = q * 256 + tid;
            int row = idx >> 3;
            int seg = idx & 7;
            cp16(gbase + (uint32_t)(row * 144 + seg * 16),
                 g_gx + ((size_t)tt * Bb + row) * G4 + bu * 32 + seg * 4);
        }
        CP_COMMIT();
    };
    prefetch_gx(0);

    for (int t = 0; t < Tt; t++) {
        const int par = t & 1;
        const __nv_bfloat16* hsrc_hi = g_hb_hi[par];
        const __nv_bfloat16* hsrc_lo = g_hb_lo[par];

        auto stage_h = [&](int ch) {
            uint32_t base = sbase + HB_OFF + (uint32_t)(ch & 3) * HCH_SZ;
#pragma unroll
            for (int q = 0; q < 4; q++) {
                int idx = q * 256 + tid;
                int sel = idx >> 9;
                int row = (idx >> 3) & 63;
                int seg = idx & 7;
                uint32_t doff = (uint32_t)(row * 72 + seg * 8) * 2 + (uint32_t)sel * HLO_SUB;
                const __nv_bfloat16* src = sel ? hsrc_lo : hsrc_hi;
                cp16(base + doff, src + (size_t)row * Hh + ch * 64 + seg * 8);
            }
            CP_COMMIT();
        };
        stage_h(0);
        stage_h(1);
        stage_h(2);

        float C[2][4];
#pragma unroll
        for (int q = 0; q < 4; q++) { C[0][q] = 0.0f; C[1][q] = 0.0f; }

        for (int ch = 0; ch < 16; ch++) {
            if (ch <= 13) cp_wait<2>();
            else if (ch == 14) cp_wait<1>();
            else cp_wait<0>();
            __syncthreads();
            // prefetch depth-3: issue overlaps this chunk's math
            if (ch <= 12) stage_h(ch + 3);

            const uint32_t abuf = sbase + HB_OFF + (uint32_t)(ch & 3) * HCH_SZ + a_lane_off;
            const uint32_t bco = (uint32_t)ch * 128;  // 64 cols * 2B

            uint32_t fa[2][2][4], fl[2][2][4], fb[2][2][2];
            ldsm_x2(fb[0][0], b_hi_base + bco);
            ldsm_x2(fb[0][1], b_lo_base + bco);
            ldsm_x4(fa[0][0], abuf);
            ldsm_x4(fa[0][1], abuf + 2304);
            ldsm_x4(fl[0][0], abuf + HLO_SUB);
            ldsm_x4(fl[0][1], abuf + HLO_SUB + 2304);
#pragma unroll
            for (int k16 = 0; k16 < 4; k16++) {
                int cur = k16 & 1;
                if (k16 < 3) {
                    int nb = cur ^ 1;
                    uint32_t kb = (uint32_t)(k16 + 1) * 32;
                    ldsm_x2(fb[nb][0], b_hi_base + bco + kb);
                    ldsm_x2(fb[nb][1], b_lo_base + bco + kb);
                    ldsm_x4(fa[nb][0], abuf + kb);
                    ldsm_x4(fa[nb][1], abuf + 2304 + kb);
                    ldsm_x4(fl[nb][0], abuf + HLO_SUB + kb);
                    ldsm_x4(fl[nb][1], abuf + HLO_SUB + 2304 + kb);
                }
#pragma unroll
                for (int mt = 0; mt < 2; mt++) {
                    mma16816(C[mt], fa[cur][mt], fb[cur][0]);
                    mma16816(C[mt], fa[cur][mt], fb[cur][1]);
                    mma16816(C[mt], fl[cur][mt], fb[cur][0]);
                }
            }
        }

        // ---- epilogue ----
        const float* gxs = reinterpret_cast<const float*>(smem + GXS_OFF + (size_t)(t & 1) * GXS_SZ);
        float v[2][4], p[2][4];
#pragma unroll
        for (int mt = 0; mt < 2; mt++) {
            int r0 = wm + mt * 16 + g;
            int r1 = r0 + 8;
            int col = wn + 2 * tq;
            v[mt][0] = C[mt][0] + gxs[r0 * 36 + col];
            v[mt][1] = C[mt][1] + gxs[r0 * 36 + col + 1];
            v[mt][2] = C[mt][2] + gxs[r1 * 36 + col];
            v[mt][3] = C[mt][3] + gxs[r1 * 36 + col + 1];
        }
#pragma unroll
        for (int mt = 0; mt < 2; mt++)
#pragma unroll
            for (int q = 0; q < 4; q++)
                p[mt][q] = __shfl_xor_sync(0xffffffffu, v[mt][q], 1);

        float ii0, ff0, cc0, oo0, ii1, ff1, cc1, oo1;
        if (myMt == 0) {
            ii0 = v[0][0]; ff0 = v[0][1]; cc0 = p[0][0]; oo0 = p[0][1];
            ii1 = v[0][2]; ff1 = v[0][3]; cc1 = p[0][2]; oo1 = p[0][3];
        } else {
            ii0 = p[1][0]; ff0 = p[1][1]; cc0 = v[1][0]; oo0 = v[1][1];
            ii1 = p[1][2]; ff1 = p[1][3]; cc1 = v[1][2]; oo1 = v[1][3];
        }

        float cn0 = fmaf(sigf(ff0), creg0, sigf(ii0) * tanhf_fast(cc0));
        float cn1 = fmaf(sigf(ff1), creg1, sigf(ii1) * tanhf_fast(cc1));
        creg0 = cn0; creg1 = cn1;
        float hn0 = sigf(oo0) * tanhf_fast(cn0);
        float hn1 = sigf(oo1) * tanhf_fast(cn1);
        hlast0 = hn0; hlast1 = hn1;

        const int np = (t + 1) & 1;
        __nv_bfloat16 h0h = __float2bfloat16(hn0);
        __nv_bfloat16 h1h = __float2bfloat16(hn1);
        g_hb_hi[np][row0 * Hh + u_glob] = h0h;
        g_hb_hi[np][row1 * Hh + u_glob] = h1h;
        g_hb_lo[np][row0 * Hh + u_glob] = __float2bfloat16(hn0 - __bfloat162float(h0h));
        g_hb_lo[np][row1 * Hh + u_glob] = __float2bfloat16(hn1 - __bfloat162float(h1h));

        if (t + 1 < Tt) {
            __syncthreads();                       // h stores + gxs reads done block-wide
            if (tid == 0) { __threadfence(); atomicAdd(&g_ctr, 1u); }
            // overlap the barrier wait with next step's gx prefetch + out stores
            prefetch_gx(t + 1);
            out[(size_t)t * (Bb * Hh) + row0 * Hh + u_glob] = hn0;
            out[(size_t)t * (Bb * Hh) + row1 * Hh + u_glob] = hn1;
            if (tid == 0) {
                unsigned tgt = (unsigned)(t + 1) * NBLK;
                while (*(volatile unsigned*)&g_ctr < tgt) nsleep();
                __threadfence();
            }
            __syncthreads();
        } else {
            out[(size_t)t * (Bb * Hh) + row0 * Hh + u_glob] = hn0;
            out[(size_t)t * (Bb * Hh) + row1 * Hh + u_glob] = hn1;
        }
    }

    // final h_T, c_T
    size_t base = (size_t)Tt * Bb * Hh;
    out[base + row0 * Hh + u_glob] = hlast0;
    out[base + row1 * Hh + u_glob] = hlast1;
    out[base + Bb * Hh + row0 * Hh + u_glob] = creg0;
    out[base + Bb * Hh + row1 * Hh + u_glob] = creg1;
}

// ---------------------------------------------------------------------------
extern "C" void kernel_launch(void* const* d_in, const int* in_sizes, int n_in,
                              void* d_out, int out_size) {
    const float* x  = (const float*)d_in[0];
    const float* Wi = (const float*)d_in[1];
    const float* bi = (const float*)d_in[2];
    const float* Wf = (const float*)d_in[3];
    const float* bf = (const float*)d_in[4];
    const float* Wc = (const float*)d_in[5];
    const float* bc = (const float*)d_in[6];
    const float* Wo = (const float*)d_in[7];
    const float* bo = (const float*)d_in[8];
    float* out = (float*)d_out;

    cudaFuncSetAttribute(gemm_x_mma, cudaFuncAttributeMaxDynamicSharedMemorySize, GX_SMEM);
    cudaFuncSetAttribute(lstm_persist, cudaFuncAttributeMaxDynamicSharedMemorySize, PERSIST_SMEM);

    repack_kernel<<<512, 256>>>(Wi, Wf, Wc, Wo, bi, bf, bc, bo);
    split_x_kernel<<<1024, 256>>>(x);
    init_state_kernel<<<512, 256>>>();

    gemm_x_mma<<<dim3(G4 / 128, (Tt * Bb) / 128), 256, GX_SMEM>>>();

    lstm_persist<<<NBLK, 256, PERSIST_SMEM>>>(out);
}

// round 8
// speedup vs baseline: 1.2049x; 1.2049x over previous
#include <cuda_runtime.h>
#include <cuda_bf16.h>
#include <cstdint>
#include <math.h>

#define Tt 512
#define Bb 64
#define Hh 1024
#define G4 4096
#define K2 2048
#define NBLK 128

// ---------------------------------------------------------------------------
// Device globals. Weight rows UNIT-MAJOR: j = u*4 + g, g in {i,f,c,o}.
// Chunk-major layouts so staging is pure cp.async.bulk byte copies.
// ---------------------------------------------------------------------------
// x chunks: [mblk=256][ch=32][128 rows * 40 cols] bf16 (rows stride 40, cols 0..31 valid)
__device__ __nv_bfloat16 g_xc_hi[(size_t)256 * 32 * 5120];
__device__ __nv_bfloat16 g_xc_lo[(size_t)256 * 32 * 5120];
// Wx chunks: [nblk=32][ch=32][128 rows * 40 cols] bf16
__device__ __nv_bfloat16 g_wc_hi[(size_t)32 * 32 * 5120];
__device__ __nv_bfloat16 g_wc_lo[(size_t)32 * 32 * 5120];
// Wh: plain row-major [4096][1024], hi/lo
__device__ __nv_bfloat16 g_Wh_hi[(size_t)G4 * Hh];
__device__ __nv_bfloat16 g_Wh_lo[(size_t)G4 * Hh];
__device__ float g_bias[G4];
// gx: [t=512][blk=128][64 rows * 36 cols] f32  (9216 B per (t,blk))
__device__ float g_gx2[(size_t)Tt * NBLK * 2304];
// h: [parity][ch=16][4608 hi + 4608 lo] bf16  (rows stride 72, 18432 B/chunk)
__device__ __nv_bfloat16 g_hbulk[2][16][9216];
__device__ volatile int g_flagsv[NBLK * 32];

// ---------------------------------------------------------------------------
// PTX helpers — non-'a' instructions only (sm_80/90 baseline)
// ---------------------------------------------------------------------------
__device__ __forceinline__ uint32_t smem_u32(const void* p) {
    uint32_t a;
    asm("{ .reg .u64 t; cvta.to.shared.u64 t, %1; cvt.u32.u64 %0, t; }" : "=r"(a) : "l"(p));
    return a;
}
__device__ __forceinline__ void cp16(uint32_t dst, const void* src) {
    asm volatile("cp.async.cg.shared.global [%0], [%1], 16;" :: "r"(dst), "l"(src) : "memory");
}
#define CP_COMMIT() asm volatile("cp.async.commit_group;" ::: "memory")
template <int N>
__device__ __forceinline__ void cp_wait() {
    asm volatile("cp.async.wait_group %0;" :: "n"(N) : "memory");
}
__device__ __forceinline__ void cp_bulk(uint32_t dst, const void* src, uint32_t bytes, uint32_t mbar) {
    asm volatile("cp.async.bulk.shared::cluster.global.mbarrier::complete_tx::bytes [%0], [%1], %2, [%3];"
                 :: "r"(dst), "l"(src), "r"(bytes), "r"(mbar) : "memory");
}
#define MBAR_INIT(mb, c)  asm volatile("mbarrier.init.shared.b64 [%0], %1;" :: "r"((uint32_t)(mb)), "r"((uint32_t)(c)) : "memory")
#define MBAR_EXPECT(mb, b) asm volatile("mbarrier.arrive.expect_tx.shared.b64 _, [%0], %1;" :: "r"((uint32_t)(mb)), "r"((uint32_t)(b)) : "memory")
#define MBAR_WAIT(mb, ph) do { \
    uint32_t _m = (uint32_t)(mb), _p = (uint32_t)(ph), _d; \
    asm volatile("{\n\t.reg .pred p;\n\tmbarrier.try_wait.parity.acquire.cta.shared::cta.b64 p, [%1], %2;\n\tselp.b32 %0, 1, 0, p;\n\t}" \
        : "=r"(_d) : "r"(_m), "r"(_p) : "memory"); \
    if (!_d) { \
        asm volatile("{\n\t.reg .pred P1;\n\tWL_%=: mbarrier.try_wait.parity.acquire.cta.shared::cta.b64 P1, [%0], %1, 0x989680;\n\t@P1 bra.uni WD_%=;\n\tbra.uni WL_%=;\n\tWD_%=:\n\t}" \
            :: "r"(_m), "r"(_p) : "memory"); \
    } \
} while (0)

__device__ __forceinline__ void mma16816(float* c, const uint32_t* a, const uint32_t* b) {
    asm volatile(
        "mma.sync.aligned.m16n8k16.row.col.f32.bf16.bf16.f32 "
        "{%0,%1,%2,%3}, {%4,%5,%6,%7}, {%8,%9}, {%0,%1,%2,%3};"
        : "+f"(c[0]), "+f"(c[1]), "+f"(c[2]), "+f"(c[3])
        : "r"(a[0]), "r"(a[1]), "r"(a[2]), "r"(a[3]), "r"(b[0]), "r"(b[1]));
}
__device__ __forceinline__ void mma16816b(float* c, const uint32_t* a, uint32_t b0, uint32_t b1) {
    asm volatile(
        "mma.sync.aligned.m16n8k16.row.col.f32.bf16.bf16.f32 "
        "{%0,%1,%2,%3}, {%4,%5,%6,%7}, {%8,%9}, {%0,%1,%2,%3};"
        : "+f"(c[0]), "+f"(c[1]), "+f"(c[2]), "+f"(c[3])
        : "r"(a[0]), "r"(a[1]), "r"(a[2]), "r"(a[3]), "r"(b0), "r"(b1));
}
__device__ __forceinline__ void ldsm_x4(uint32_t* r, uint32_t addr) {
    asm volatile("ldmatrix.sync.aligned.m8n8.x4.shared.b16 {%0,%1,%2,%3}, [%4];"
                 : "=r"(r[0]), "=r"(r[1]), "=r"(r[2]), "=r"(r[3]) : "r"(addr));
}
__device__ __forceinline__ void ldsm_x2(uint32_t* r, uint32_t addr) {
    asm volatile("ldmatrix.sync.aligned.m8n8.x2.shared.b16 {%0,%1}, [%2];"
                 : "=r"(r[0]), "=r"(r[1]) : "r"(addr));
}
__device__ __forceinline__ void nsleep() { asm volatile("nanosleep.u32 40;"); }

__device__ __forceinline__ float sigf(float v) { return 1.0f / (1.0f + __expf(-v)); }
__device__ __forceinline__ float tanhf_fast(float v) {
    float e = __expf(-2.0f * fabsf(v));
    float r = (1.0f - e) / (1.0f + e);
    return (v >= 0.0f) ? r : -r;
}

// ---------------------------------------------------------------------------
// Prep kernels
// ---------------------------------------------------------------------------
__global__ void split_x_kernel(const float* __restrict__ x) {
    size_t total = (size_t)Tt * Bb * Hh;
    size_t stride = (size_t)gridDim.x * blockDim.x;
    for (size_t i = (size_t)blockIdx.x * blockDim.x + threadIdx.x; i < total; i += stride) {
        float v = x[i];
        __nv_bfloat16 hi = __float2bfloat16(v);
        __nv_bfloat16 lo = __float2bfloat16(v - __bfloat162float(hi));
        size_t m = i >> 10;            // row (t*64+b)
        int k = (int)(i & 1023);
        size_t dst = ((m >> 7) * 32 + (k >> 5)) * 5120 + (m & 127) * 40 + (k & 31);
        g_xc_hi[dst] = hi;
        g_xc_lo[dst] = lo;
    }
}

__global__ void repack_kernel(const float* __restrict__ Wi, const float* __restrict__ Wf,
                              const float* __restrict__ Wc, const float* __restrict__ Wo,
                              const float* __restrict__ bi, const float* __restrict__ bf,
                              const float* __restrict__ bc, const float* __restrict__ bo) {
    size_t total = (size_t)G4 * K2;
    size_t stride = (size_t)gridDim.x * blockDim.x;
    for (size_t idx = (size_t)blockIdx.x * blockDim.x + threadIdx.x; idx < total; idx += stride) {
        int j = (int)(idx / K2);
        int k = (int)(idx % K2);
        int u = j >> 2, g = j & 3;
        const float* src = (g == 0) ? Wi : (g == 1) ? Wf : (g == 2) ? Wc : Wo;
        float v = src[(size_t)u * K2 + k];
        __nv_bfloat16 hi = __float2bfloat16(v);
        __nv_bfloat16 lo = __float2bfloat16(v - __bfloat162float(hi));
        if (k < Hh) {
            size_t dst = ((size_t)(j >> 7) * 32 + (k >> 5)) * 5120 + (j & 127) * 40 + (k & 31);
            g_wc_hi[dst] = hi;
            g_wc_lo[dst] = lo;
        } else {
            g_Wh_hi[(size_t)j * Hh + (k - Hh)] = hi;
            g_Wh_lo[(size_t)j * Hh + (k - Hh)] = lo;
        }
    }
    for (int j = blockIdx.x * blockDim.x + threadIdx.x; j < G4; j += (int)stride) {
        int u = j >> 2, g = j & 3;
        const float* sb = (g == 0) ? bi : (g == 1) ? bf : (g == 2) ? bc : bo;
        g_bias[j] = sb[u];
    }
}

__global__ void init_state_kernel() {
    int i = blockIdx.x * blockDim.x + threadIdx.x;
    int stride = gridDim.x * blockDim.x;
    __nv_bfloat16 z = __float2bfloat16(0.0f);
    for (int k = i; k < 16 * 9216; k += stride) {
        g_hbulk[0][k / 9216][k % 9216] = z;
    }
    for (int k = i; k < NBLK * 32; k += stride) g_flagsv[k] = 0;
}

// ---------------------------------------------------------------------------
// x-GEMM: gx = x @ Wx^T + b, bf16 hi/lo 3-product via mma.sync.
// CTA 128x128, 8 warps, warp tile 64x32. K chunks of 32, 2-slot ring staged
// with cp.async.bulk (4 bulks/chunk). 2 CTAs/SM.
// ---------------------------------------------------------------------------
#define RS 40
#define ARR (128 * RS * 2)              // 10240 B
#define GX_MB (2 * 4 * ARR)             // mbarriers after buffers
#define GX_SMEM (GX_MB + 16)

__global__ __launch_bounds__(256, 2) void gemm_x_mma() {
    extern __shared__ char smem[];
    const uint32_t sbase = smem_u32(smem);
    const int tid = threadIdx.x;
    const int w = tid >> 5;
    const int lane = tid & 31;
    const int g = lane >> 2;
    const int t = lane & 3;
    const int nblk = blockIdx.x;
    const int mblk = blockIdx.y;
    const int n0 = nblk * 128;
    const int m0 = mblk * 128;
    const int wm = (w >> 2) * 64;
    const int wn = (w & 3) * 32;
    const int lrow = (lane & 7) + ((lane >> 3) & 1) * 8;
    const int lcol = (lane >> 4) * 8;

    const uint32_t mb0 = sbase + GX_MB;
    const uint32_t mb1 = sbase + GX_MB + 8;
    if (tid == 0) { MBAR_INIT(mb0, 1); MBAR_INIT(mb1, 1); }
    __syncthreads();

    auto stage = [&](int ch) {
        uint32_t base = sbase + (uint32_t)(ch & 1) * 4 * ARR;
        uint32_t mb = (ch & 1) ? mb1 : mb0;
        MBAR_EXPECT(mb, 4 * ARR);
        const __nv_bfloat16* ah = g_xc_hi + ((size_t)mblk * 32 + ch) * 5120;
        const __nv_bfloat16* al = g_xc_lo + ((size_t)mblk * 32 + ch) * 5120;
        const __nv_bfloat16* bh = g_wc_hi + ((size_t)nblk * 32 + ch) * 5120;
        const __nv_bfloat16* bl = g_wc_lo + ((size_t)nblk * 32 + ch) * 5120;
        cp_bulk(base + 0 * ARR, ah, ARR, mb);
        cp_bulk(base + 1 * ARR, al, ARR, mb);
        cp_bulk(base + 2 * ARR, bh, ARR, mb);
        cp_bulk(base + 3 * ARR, bl, ARR, mb);
    };

    float C[4][4][4];
#pragma unroll
    for (int i = 0; i < 4; i++)
#pragma unroll
        for (int j = 0; j < 4; j++)
#pragma unroll
            for (int q = 0; q < 4; q++) C[i][j][q] = 0.0f;

    const uint32_t a_off = (uint32_t)((wm + lrow) * RS + lcol) * 2;
    const uint32_t b_off = (uint32_t)((wn + lrow) * RS + lcol) * 2;

    if (tid == 0) stage(0);
    for (int ch = 0; ch < 32; ch++) {
        MBAR_WAIT((ch & 1) ? mb1 : mb0, (ch >> 1) & 1);
        __syncthreads();
        if (tid == 0 && ch < 31) stage(ch + 1);
        const uint32_t buf = sbase + (uint32_t)(ch & 1) * 4 * ARR;
#pragma unroll
        for (int kk = 0; kk < 32; kk += 16) {
            uint32_t ah[4][4], al[4][4], bh[2][4], bl[2][4];
#pragma unroll
            for (int mt = 0; mt < 4; mt++) {
                ldsm_x4(ah[mt], buf + 0 * ARR + a_off + (uint32_t)(mt * 16 * RS + kk) * 2);
                ldsm_x4(al[mt], buf + 1 * ARR + a_off + (uint32_t)(mt * 16 * RS + kk) * 2);
            }
#pragma unroll
            for (int p = 0; p < 2; p++) {
                ldsm_x4(bh[p], buf + 2 * ARR + b_off + (uint32_t)(p * 16 * RS + kk) * 2);
                ldsm_x4(bl[p], buf + 3 * ARR + b_off + (uint32_t)(p * 16 * RS + kk) * 2);
            }
#pragma unroll
            for (int mt = 0; mt < 4; mt++)
#pragma unroll
                for (int nt = 0; nt < 4; nt++) {
                    int p = nt >> 1, s = nt & 1;
                    mma16816b(C[mt][nt], ah[mt], bh[p][s], bh[p][s + 2]);
                    mma16816b(C[mt][nt], ah[mt], bl[p][s], bl[p][s + 2]);
                    mma16816b(C[mt][nt], al[mt], bh[p][s], bh[p][s + 2]);
                }
        }
        __syncthreads();
    }

    // Epilogue: add bias, store into chunk-major gx2
#pragma unroll
    for (int mt = 0; mt < 4; mt++) {
        int row = m0 + wm + mt * 16 + g;
        int t_idx = row >> 6;
        int batch = row & 63;
#pragma unroll
        for (int nt = 0; nt < 4; nt++) {
            int col = n0 + wn + nt * 8 + 2 * t;
            int buI = col >> 5;
            int cs = col & 31;
            float2 bv = *reinterpret_cast<const float2*>(g_bias + col);
            float2 o0 = { C[mt][nt][0] + bv.x, C[mt][nt][1] + bv.y };
            float2 o1 = { C[mt][nt][2] + bv.x, C[mt][nt][3] + bv.y };
            float* dst = g_gx2 + ((size_t)t_idx * NBLK + buI) * 2304;
            *reinterpret_cast<float2*>(dst + batch * 36 + cs) = o0;
            *reinterpret_cast<float2*>(dst + (batch + 8) * 36 + cs) = o1;
        }
    }
}

// ---------------------------------------------------------------------------
// Persistent recurrent kernel: 128 blocks x 256 threads, all 512 steps.
// SMEM (bytes):
//   WH hi [32][1032]bf16 @ 0        (66048)
//   WH lo                @ 66048    (66048)
//   H ring: 4 x 18432 (hi 9216 + lo 9216, rows stride 72) @ 132096 (73728)
//   GXS [64][36]f32 @ 205824 (9216)
//   mbarriers @ 215040 (5 x 8)      -> total 215088
// ---------------------------------------------------------------------------
#define WH_HI_OFF 0
#define WH_LO_OFF 66048
#define HB_OFF    132096
#define HCH_SZ    18432
#define HLO_SUB   9216
#define GXS_OFF   205824
#define PMB_OFF   215040
#define PERSIST_SMEM 215088

__global__ __launch_bounds__(256, 1) void lstm_persist(float* __restrict__ out) {
    extern __shared__ char smem[];
    const uint32_t sbase = smem_u32(smem);
    const int tid = threadIdx.x;
    const int bu = blockIdx.x;
    const int w = tid >> 5;
    const int lane = tid & 31;
    const int g = lane >> 2;
    const int tq = lane & 3;
    const int wm = (w >> 2) * 32;   // 0 or 32
    const int wn = (w & 3) * 8;     // 0,8,16,24

    if (tid == 0) {
#pragma unroll
        for (int s = 0; s < 5; s++) MBAR_INIT(sbase + PMB_OFF + s * 8, 1);
    }

    // ---- load Wh slice into smem (once, cp16 path) ----
    {
        const __nv_bfloat16* shi = g_Wh_hi + (size_t)bu * 32 * Hh;
        const __nv_bfloat16* slo = g_Wh_lo + (size_t)bu * 32 * Hh;
#pragma unroll
        for (int q = 0; q < 16; q++) {
            int idx = q * 256 + tid;
            int row = idx >> 7;
            int seg = idx & 127;
            uint32_t doff = (uint32_t)(row * 1032 + seg * 8) * 2;
            cp16(sbase + WH_HI_OFF + doff, shi + (size_t)row * Hh + seg * 8);
            cp16(sbase + WH_LO_OFF + doff, slo + (size_t)row * Hh + seg * 8);
        }
        CP_COMMIT();
        cp_wait<0>();
    }
    __syncthreads();

    const int lrow = (lane & 7) + ((lane >> 3) & 1) * 8;
    const int lcol = (lane >> 4) * 8;
    const uint32_t a_lane_off = (uint32_t)((wm + lrow) * 72 + lcol) * 2;
    const uint32_t b_lane_off = (uint32_t)((wn + (lane & 7)) * 1032 + ((lane >> 3) & 1) * 8) * 2;
    const uint32_t b_hi_base = sbase + WH_HI_OFF + b_lane_off;
    const uint32_t b_lo_base = sbase + WH_LO_OFF + b_lane_off;

    const int myMt = tq & 1;
    const int row0 = wm + myMt * 16 + g;
    const int row1 = row0 + 8;
    const int u_glob = bu * 8 + (wn >> 2) + (tq >> 1);
    const int u_ch = u_glob >> 6;
    const int u_c = u_glob & 63;

    float creg0 = 0.0f, creg1 = 0.0f;
    float hlast0 = 0.0f, hlast1 = 0.0f;
    const float* gxs = reinterpret_cast<const float*>(smem + GXS_OFF);
    const uint32_t mb_gx = sbase + PMB_OFF + 32;

    for (int t = 0; t < Tt; t++) {
        const int par = t & 1;
        const char* hsrc = reinterpret_cast<const char*>(&g_hbulk[par][0][0]);

        if (tid == 0) {
            MBAR_EXPECT(mb_gx, 9216);
            cp_bulk(sbase + GXS_OFF, g_gx2 + ((size_t)t * NBLK + bu) * 2304, 9216, mb_gx);
#pragma unroll
            for (int s = 0; s < 3; s++) {
                uint32_t mb = sbase + PMB_OFF + s * 8;
                MBAR_EXPECT(mb, HCH_SZ);
                cp_bulk(sbase + HB_OFF + (uint32_t)s * HCH_SZ, hsrc + (size_t)s * HCH_SZ, HCH_SZ, mb);
            }
        }

        float C[2][4];
#pragma unroll
        for (int q = 0; q < 4; q++) { C[0][q] = 0.0f; C[1][q] = 0.0f; }

        for (int ch = 0; ch < 16; ch++) {
            MBAR_WAIT(sbase + PMB_OFF + (ch & 3) * 8, (ch >> 2) & 1);
            __syncthreads();
            if (tid == 0 && ch < 13) {
                int nc = ch + 3;
                uint32_t mb = sbase + PMB_OFF + (nc & 3) * 8;
                MBAR_EXPECT(mb, HCH_SZ);
                cp_bulk(sbase + HB_OFF + (uint32_t)(nc & 3) * HCH_SZ, hsrc + (size_t)nc * HCH_SZ, HCH_SZ, mb);
            }

            const uint32_t abuf = sbase + HB_OFF + (uint32_t)(ch & 3) * HCH_SZ + a_lane_off;
            const uint32_t bco = (uint32_t)ch * 128;  // 64 cols * 2B

            uint32_t fa[2][2][4], fl[2][2][4], fb[2][2][2];
            ldsm_x2(fb[0][0], b_hi_base + bco);
            ldsm_x2(fb[0][1], b_lo_base + bco);
            ldsm_x4(fa[0][0], abuf);
            ldsm_x4(fa[0][1], abuf + 2304);
            ldsm_x4(fl[0][0], abuf + HLO_SUB);
            ldsm_x4(fl[0][1], abuf + HLO_SUB + 2304);
#pragma unroll
            for (int k16 = 0; k16 < 4; k16++) {
                int cur = k16 & 1;
                if (k16 < 3) {
                    int nb = cur ^ 1;
                    uint32_t kb = (uint32_t)(k16 + 1) * 32;
                    ldsm_x2(fb[nb][0], b_hi_base + bco + kb);
                    ldsm_x2(fb[nb][1], b_lo_base + bco + kb);
                    ldsm_x4(fa[nb][0], abuf + kb);
                    ldsm_x4(fa[nb][1], abuf + 2304 + kb);
                    ldsm_x4(fl[nb][0], abuf + HLO_SUB + kb);
                    ldsm_x4(fl[nb][1], abuf + HLO_SUB + 2304 + kb);
                }
#pragma unroll
                for (int mt = 0; mt < 2; mt++) {
                    mma16816(C[mt], fa[cur][mt], fb[cur][0]);
                    mma16816(C[mt], fa[cur][mt], fb[cur][1]);
                    mma16816(C[mt], fl[cur][mt], fb[cur][0]);
                }
            }
        }

        // ---- epilogue ----
        MBAR_WAIT(mb_gx, t & 1);
        float v[2][4], p[2][4];
#pragma unroll
        for (int mt = 0; mt < 2; mt++) {
            int r0 = wm + mt * 16 + g;
            int r1 = r0 + 8;
            int col = wn + 2 * tq;
            v[mt][0] = C[mt][0] + gxs[r0 * 36 + col];
            v[mt][1] = C[mt][1] + gxs[r0 * 36 + col + 1];
            v[mt][2] = C[mt][2] + gxs[r1 * 36 + col];
            v[mt][3] = C[mt][3] + gxs[r1 * 36 + col + 1];
        }
#pragma unroll
        for (int mt = 0; mt < 2; mt++)
#pragma unroll
            for (int q = 0; q < 4; q++)
                p[mt][q] = __shfl_xor_sync(0xffffffffu, v[mt][q], 1);

        float ii0, ff0, cc0, oo0, ii1, ff1, cc1, oo1;
        if (myMt == 0) {
            ii0 = v[0][0]; ff0 = v[0][1]; cc0 = p[0][0]; oo0 = p[0][1];
            ii1 = v[0][2]; ff1 = v[0][3]; cc1 = p[0][2]; oo1 = p[0][3];
        } else {
            ii0 = p[1][0]; ff0 = p[1][1]; cc0 = v[1][0]; oo0 = v[1][1];
            ii1 = p[1][2]; ff1 = p[1][3]; cc1 = v[1][2]; oo1 = v[1][3];
        }

        float cn0 = fmaf(sigf(ff0), creg0, sigf(ii0) * tanhf_fast(cc0));
        float cn1 = fmaf(sigf(ff1), creg1, sigf(ii1) * tanhf_fast(cc1));
        creg0 = cn0; creg1 = cn1;
        float hn0 = sigf(oo0) * tanhf_fast(cn0);
        float hn1 = sigf(oo1) * tanhf_fast(cn1);
        hlast0 = hn0; hlast1 = hn1;

        const int np = (t + 1) & 1;
        __nv_bfloat16 h0h = __float2bfloat16(hn0);
        __nv_bfloat16 h1h = __float2bfloat16(hn1);
        __nv_bfloat16* hb = &g_hbulk[np][u_ch][0];
        hb[row0 * 72 + u_c] = h0h;
        hb[row1 * 72 + u_c] = h1h;
        hb[4608 + row0 * 72 + u_c] = __float2bfloat16(hn0 - __bfloat162float(h0h));
        hb[4608 + row1 * 72 + u_c] = __float2bfloat16(hn1 - __bfloat162float(h1h));

        if (t + 1 < Tt) {
            __syncthreads();   // all h stores done block-wide
            if (tid == 0) { __threadfence(); g_flagsv[bu * 32] = t + 1; }
            // hide out-seq stores in the barrier window
            out[(size_t)t * (Bb * Hh) + row0 * Hh + u_glob] = hn0;
            out[(size_t)t * (Bb * Hh) + row1 * Hh + u_glob] = hn1;
            if (tid < NBLK) {
                while (g_flagsv[tid * 32] < t + 1) nsleep();
                __threadfence();
            }
            __syncthreads();
        } else {
            out[(size_t)t * (Bb * Hh) + row0 * Hh + u_glob] = hn0;
            out[(size_t)t * (Bb * Hh) + row1 * Hh + u_glob] = hn1;
        }
    }

    // final h_T, c_T
    size_t base = (size_t)Tt * Bb * Hh;
    out[base + row0 * Hh + u_glob] = hlast0;
    out[base + row1 * Hh + u_glob] = hlast1;
    out[base + Bb * Hh + row0 * Hh + u_glob] = creg0;
    out[base + Bb * Hh + row1 * Hh + u_glob] = creg1;
}

// ---------------------------------------------------------------------------
extern "C" void kernel_launch(void* const* d_in, const int* in_sizes, int n_in,
                              void* d_out, int out_size) {
    const float* x  = (const float*)d_in[0];
    const float* Wi = (const float*)d_in[1];
    const float* bi = (const float*)d_in[2];
    const float* Wf = (const float*)d_in[3];
    const float* bf = (const float*)d_in[4];
    const float* Wc = (const float*)d_in[5];
    const float* bc = (const float*)d_in[6];
    const float* Wo = (const float*)d_in[7];
    const float* bo = (const float*)d_in[8];
    float* out = (float*)d_out;

    cudaFuncSetAttribute(gemm_x_mma, cudaFuncAttributeMaxDynamicSharedMemorySize, GX_SMEM);
    cudaFuncSetAttribute(lstm_persist, cudaFuncAttributeMaxDynamicSharedMemorySize, PERSIST_SMEM);

    repack_kernel<<<512, 256>>>(Wi, Wf, Wc, Wo, bi, bf, bc, bo);
    split_x_kernel<<<1024, 256>>>(x);
    init_state_kernel<<<512, 256>>>();

    gemm_x_mma<<<dim3(G4 / 128, (Tt * Bb) / 128), 256, GX_SMEM>>>();

    lstm_persist<<<NBLK, 256, PERSIST_SMEM>>>(out);
}

// round 9
// speedup vs baseline: 1.9156x; 1.5898x over previous
#include <cuda_runtime.h>
#include <cuda_fp16.h>
#include <cstdint>
#include <math.h>

#define Tt 512
#define Bb 64
#define Hh 1024
#define G4 4096
#define K2 2048
#define NBLK 128

// ---------------------------------------------------------------------------
// Device globals. Weight rows UNIT-MAJOR: j = u*4 + g, g in {i,f,c,o}.
// Chunk-major fp16 layouts; staging is pure cp.async.bulk byte copies.
// ---------------------------------------------------------------------------
// x chunks: [mblk=256][ch=32][128 rows * 40 cols] fp16
__device__ __align__(128) __half g_xc[(size_t)256 * 32 * 5120];
// Wx chunks: [nblk=32][ch=32][128 rows * 40 cols] fp16
__device__ __align__(128) __half g_wc[(size_t)32 * 32 * 5120];
// Wh: row-major [4096][1024] fp16
__device__ __align__(128) __half g_Wh[(size_t)G4 * Hh];
__device__ float g_bias[G4];
// gx: [t=512][blk=128][64 rows * 36 cols] f32 (9216 B per (t,blk))
__device__ __align__(128) float g_gx2[(size_t)Tt * NBLK * 2304];
// h: [parity][ch=16][64 rows * 72 stride] fp16 (9216 B per chunk)
__device__ __align__(128) __half g_hbulk[2][16][4608];
__device__ volatile int g_flagsv[NBLK * 32];

// ---------------------------------------------------------------------------
// PTX helpers — non-'a' instructions only
// ---------------------------------------------------------------------------
__device__ __forceinline__ uint32_t smem_u32(const void* p) {
    uint32_t a;
    asm("{ .reg .u64 t; cvta.to.shared.u64 t, %1; cvt.u32.u64 %0, t; }" : "=r"(a) : "l"(p));
    return a;
}
__device__ __forceinline__ void cp16(uint32_t dst, const void* src) {
    asm volatile("cp.async.cg.shared.global [%0], [%1], 16;" :: "r"(dst), "l"(src) : "memory");
}
#define CP_COMMIT() asm volatile("cp.async.commit_group;" ::: "memory")
template <int N>
__device__ __forceinline__ void cp_wait() {
    asm volatile("cp.async.wait_group %0;" :: "n"(N) : "memory");
}
__device__ __forceinline__ void cp_bulk(uint32_t dst, const void* src, uint32_t bytes, uint32_t mbar) {
    asm volatile("cp.async.bulk.shared::cluster.global.mbarrier::complete_tx::bytes [%0], [%1], %2, [%3];"
                 :: "r"(dst), "l"(src), "r"(bytes), "r"(mbar) : "memory");
}
#define MBAR_INIT(mb, c)  asm volatile("mbarrier.init.shared.b64 [%0], %1;" :: "r"((uint32_t)(mb)), "r"((uint32_t)(c)) : "memory")
#define MBAR_EXPECT(mb, b) asm volatile("mbarrier.arrive.expect_tx.shared.b64 _, [%0], %1;" :: "r"((uint32_t)(mb)), "r"((uint32_t)(b)) : "memory")
#define MBAR_WAIT(mb, ph) do { \
    uint32_t _m = (uint32_t)(mb), _p = (uint32_t)(ph), _d; \
    asm volatile("{\n\t.reg .pred p;\n\tmbarrier.try_wait.parity.acquire.cta.shared::cta.b64 p, [%1], %2;\n\tselp.b32 %0, 1, 0, p;\n\t}" \
        : "=r"(_d) : "r"(_m), "r"(_p) : "memory"); \
    if (!_d) { \
        asm volatile("{\n\t.reg .pred P1;\n\tWL_%=: mbarrier.try_wait.parity.acquire.cta.shared::cta.b64 P1, [%0], %1, 0x989680;\n\t@P1 bra.uni WD_%=;\n\tbra.uni WL_%=;\n\tWD_%=:\n\t}" \
            :: "r"(_m), "r"(_p) : "memory"); \
    } \
} while (0)

__device__ __forceinline__ void mma_f16(float* c, const uint32_t* a, const uint32_t* b) {
    asm volatile(
        "mma.sync.aligned.m16n8k16.row.col.f32.f16.f16.f32 "
        "{%0,%1,%2,%3}, {%4,%5,%6,%7}, {%8,%9}, {%0,%1,%2,%3};"
        : "+f"(c[0]), "+f"(c[1]), "+f"(c[2]), "+f"(c[3])
        : "r"(a[0]), "r"(a[1]), "r"(a[2]), "r"(a[3]), "r"(b[0]), "r"(b[1]));
}
__device__ __forceinline__ void mma_f16b(float* c, const uint32_t* a, uint32_t b0, uint32_t b1) {
    asm volatile(
        "mma.sync.aligned.m16n8k16.row.col.f32.f16.f16.f32 "
        "{%0,%1,%2,%3}, {%4,%5,%6,%7}, {%8,%9}, {%0,%1,%2,%3};"
        : "+f"(c[0]), "+f"(c[1]), "+f"(c[2]), "+f"(c[3])
        : "r"(a[0]), "r"(a[1]), "r"(a[2]), "r"(a[3]), "r"(b0), "r"(b1));
}
__device__ __forceinline__ void ldsm_x4(uint32_t* r, uint32_t addr) {
    asm volatile("ldmatrix.sync.aligned.m8n8.x4.shared.b16 {%0,%1,%2,%3}, [%4];"
                 : "=r"(r[0]), "=r"(r[1]), "=r"(r[2]), "=r"(r[3]) : "r"(addr));
}
__device__ __forceinline__ void ldsm_x2(uint32_t* r, uint32_t addr) {
    asm volatile("ldmatrix.sync.aligned.m8n8.x2.shared.b16 {%0,%1}, [%2];"
                 : "=r"(r[0]), "=r"(r[1]) : "r"(addr));
}
__device__ __forceinline__ void nsleep() { asm volatile("nanosleep.u32 40;"); }

__device__ __forceinline__ float sigf(float v) { return 1.0f / (1.0f + __expf(-v)); }
__device__ __forceinline__ float tanhf_fast(float v) {
    float e = __expf(-2.0f * fabsf(v));
    float r = (1.0f - e) / (1.0f + e);
    return (v >= 0.0f) ? r : -r;
}

// ---------------------------------------------------------------------------
// Prep kernels
// ---------------------------------------------------------------------------
__global__ void split_x_kernel(const float* __restrict__ x) {
    size_t total = (size_t)Tt * Bb * Hh;
    size_t stride = (size_t)gridDim.x * blockDim.x;
    for (size_t i = (size_t)blockIdx.x * blockDim.x + threadIdx.x; i < total; i += stride) {
        float v = x[i];
        size_t m = i >> 10;
        int k = (int)(i & 1023);
        size_t dst = ((m >> 7) * 32 + (k >> 5)) * 5120 + (m & 127) * 40 + (k & 31);
        g_xc[dst] = __float2half(v);
    }
}

__global__ void repack_kernel(const float* __restrict__ Wi, const float* __restrict__ Wf,
                              const float* __restrict__ Wc, const float* __restrict__ Wo,
                              const float* __restrict__ bi, const float* __restrict__ bf,
                              const float* __restrict__ bc, const float* __restrict__ bo) {
    size_t total = (size_t)G4 * K2;
    size_t stride = (size_t)gridDim.x * blockDim.x;
    for (size_t idx = (size_t)blockIdx.x * blockDim.x + threadIdx.x; idx < total; idx += stride) {
        int j = (int)(idx / K2);
        int k = (int)(idx % K2);
        int u = j >> 2, g = j & 3;
        const float* src = (g == 0) ? Wi : (g == 1) ? Wf : (g == 2) ? Wc : Wo;
        float v = src[(size_t)u * K2 + k];
        if (k < Hh) {
            size_t dst = ((size_t)(j >> 7) * 32 + (k >> 5)) * 5120 + (j & 127) * 40 + (k & 31);
            g_wc[dst] = __float2half(v);
        } else {
            g_Wh[(size_t)j * Hh + (k - Hh)] = __float2half(v);
        }
    }
    for (int j = blockIdx.x * blockDim.x + threadIdx.x; j < G4; j += (int)stride) {
        int u = j >> 2, g = j & 3;
        const float* sb = (g == 0) ? bi : (g == 1) ? bf : (g == 2) ? bc : bo;
        g_bias[j] = sb[u];
    }
}

__global__ void init_state_kernel() {
    int i = blockIdx.x * blockDim.x + threadIdx.x;
    int stride = gridDim.x * blockDim.x;
    __half z = __float2half(0.0f);
    for (int k = i; k < 16 * 4608; k += stride) {
        g_hbulk[0][k / 4608][k % 4608] = z;
    }
    for (int k = i; k < NBLK * 32; k += stride) g_flagsv[k] = 0;
}

// ---------------------------------------------------------------------------
// x-GEMM: gx = x @ Wx^T + b, fp16 single-product via mma.sync.
// CTA 128x128, 8 warps, warp tile 64x32. K chunks of 32, 4-slot bulk ring,
// 2 CTAs/SM.
// ---------------------------------------------------------------------------
#define RS 40
#define ARR (128 * RS * 2)              // 10240 B
#define SLOT (2 * ARR)                  // A + B
#define GX_MB (4 * SLOT)                // 81920
#define GX_SMEM (GX_MB + 32)

__global__ __launch_bounds__(256, 2) void gemm_x_mma() {
    extern __shared__ char smem[];
    const uint32_t sbase = smem_u32(smem);
    const int tid = threadIdx.x;
    const int w = tid >> 5;
    const int lane = tid & 31;
    const int g = lane >> 2;
    const int t = lane & 3;
    const int nblk = blockIdx.x;
    const int mblk = blockIdx.y;
    const int n0 = nblk * 128;
    const int m0 = mblk * 128;
    const int wm = (w >> 2) * 64;
    const int wn = (w & 3) * 32;
    const int lrow = (lane & 7) + ((lane >> 3) & 1) * 8;
    const int lcol = (lane >> 4) * 8;

    if (tid == 0) {
#pragma unroll
        for (int s = 0; s < 4; s++) MBAR_INIT(sbase + GX_MB + s * 8, 1);
    }
    __syncthreads();

    auto stage = [&](int ch) {
        uint32_t base = sbase + (uint32_t)(ch & 3) * SLOT;
        uint32_t mb = sbase + GX_MB + (ch & 3) * 8;
        MBAR_EXPECT(mb, SLOT);
        cp_bulk(base, g_xc + ((size_t)mblk * 32 + ch) * 5120, ARR, mb);
        cp_bulk(base + ARR, g_wc + ((size_t)nblk * 32 + ch) * 5120, ARR, mb);
    };

    float C[4][4][4];
#pragma unroll
    for (int i = 0; i < 4; i++)
#pragma unroll
        for (int j = 0; j < 4; j++)
#pragma unroll
            for (int q = 0; q < 4; q++) C[i][j][q] = 0.0f;

    const uint32_t a_off = (uint32_t)((wm + lrow) * RS + lcol) * 2;
    const uint32_t b_off = (uint32_t)((wn + lrow) * RS + lcol) * 2;

    if (tid == 0) { stage(0); stage(1); stage(2); }
    for (int ch = 0; ch < 32; ch++) {
        MBAR_WAIT(sbase + GX_MB + (ch & 3) * 8, (ch >> 2) & 1);
        __syncthreads();
        if (tid == 0 && ch < 29) stage(ch + 3);
        const uint32_t buf = sbase + (uint32_t)(ch & 3) * SLOT;
#pragma unroll
        for (int kk = 0; kk < 32; kk += 16) {
            uint32_t ah[4][4], bh[2][4];
#pragma unroll
            for (int mt = 0; mt < 4; mt++)
                ldsm_x4(ah[mt], buf + a_off + (uint32_t)(mt * 16 * RS + kk) * 2);
#pragma unroll
            for (int p = 0; p < 2; p++)
                ldsm_x4(bh[p], buf + ARR + b_off + (uint32_t)(p * 16 * RS + kk) * 2);
#pragma unroll
            for (int mt = 0; mt < 4; mt++)
#pragma unroll
                for (int nt = 0; nt < 4; nt++) {
                    int p = nt >> 1, s = nt & 1;
                    mma_f16b(C[mt][nt], ah[mt], bh[p][s], bh[p][s + 2]);
                }
        }
        __syncthreads();
    }

    // Epilogue: add bias, store into chunk-major gx2
#pragma unroll
    for (int mt = 0; mt < 4; mt++) {
        int row = m0 + wm + mt * 16 + g;
        int t_idx = row >> 6;
        int batch = row & 63;
#pragma unroll
        for (int nt = 0; nt < 4; nt++) {
            int col = n0 + wn + nt * 8 + 2 * t;
            int buI = col >> 5;
            int cs = col & 31;
            float2 bv = *reinterpret_cast<const float2*>(g_bias + col);
            float2 o0 = { C[mt][nt][0] + bv.x, C[mt][nt][1] + bv.y };
            float2 o1 = { C[mt][nt][2] + bv.x, C[mt][nt][3] + bv.y };
            float* dst = g_gx2 + ((size_t)t_idx * NBLK + buI) * 2304;
            *reinterpret_cast<float2*>(dst + batch * 36 + cs) = o0;
            *reinterpret_cast<float2*>(dst + (batch + 8) * 36 + cs) = o1;
        }
    }
}

// ---------------------------------------------------------------------------
// Persistent recurrent kernel: 128 blocks x 256 threads, all 512 steps.
// fp16 single-product. SMEM (bytes):
//   WH [32][1032] fp16 @ 0          (66048)
//   H ring: 4 x 9216 @ 66048        (36864)
//   GXS [64][36] f32 @ 102912       (9216)
//   mbarriers @ 112128 (5 x 8)      -> total 112176
// ---------------------------------------------------------------------------
#define WH_OFF 0
#define HB_OFF 66048
#define HCH_SZ 9216
#define GXS_OFF 102912
#define PMB_OFF 112128
#define PERSIST_SMEM 112176

__global__ __launch_bounds__(256, 1) void lstm_persist(float* __restrict__ out) {
    extern __shared__ char smem[];
    const uint32_t sbase = smem_u32(smem);
    const int tid = threadIdx.x;
    const int bu = blockIdx.x;
    const int w = tid >> 5;
    const int lane = tid & 31;
    const int g = lane >> 2;
    const int tq = lane & 3;
    const int wm = (w >> 2) * 32;   // 0 or 32
    const int wn = (w & 3) * 8;     // 0,8,16,24

    if (tid == 0) {
#pragma unroll
        for (int s = 0; s < 5; s++) MBAR_INIT(sbase + PMB_OFF + s * 8, 1);
    }

    // ---- load Wh slice into smem (once) ----
    {
        const __half* ws = g_Wh + (size_t)bu * 32 * Hh;
#pragma unroll
        for (int q = 0; q < 16; q++) {
            int idx = q * 256 + tid;
            int row = idx >> 7;
            int seg = idx & 127;
            cp16(sbase + WH_OFF + (uint32_t)(row * 1032 + seg * 8) * 2,
                 ws + (size_t)row * Hh + seg * 8);
        }
        CP_COMMIT();
        cp_wait<0>();
    }
    __syncthreads();

    const int lrow = (lane & 7) + ((lane >> 3) & 1) * 8;
    const int lcol = (lane >> 4) * 8;
    const uint32_t a_lane_off = (uint32_t)((wm + lrow) * 72 + lcol) * 2;
    const uint32_t b_lane_off = (uint32_t)((wn + (lane & 7)) * 1032 + ((lane >> 3) & 1) * 8) * 2;
    const uint32_t b_base = sbase + WH_OFF + b_lane_off;

    const int myMt = tq & 1;
    const int row0 = wm + myMt * 16 + g;
    const int row1 = row0 + 8;
    const int u_glob = bu * 8 + (wn >> 2) + (tq >> 1);
    const int u_ch = u_glob >> 6;
    const int u_c = u_glob & 63;

    float creg0 = 0.0f, creg1 = 0.0f;
    float hlast0 = 0.0f, hlast1 = 0.0f;
    const float* gxs = reinterpret_cast<const float*>(smem + GXS_OFF);
    const uint32_t mb_gx = sbase + PMB_OFF + 32;

    for (int t = 0; t < Tt; t++) {
        const int par = t & 1;
        const char* hsrc = reinterpret_cast<const char*>(&g_hbulk[par][0][0]);

        if (tid == 0) {
            MBAR_EXPECT(mb_gx, 9216);
            cp_bulk(sbase + GXS_OFF, g_gx2 + ((size_t)t * NBLK + bu) * 2304, 9216, mb_gx);
#pragma unroll
            for (int s = 0; s < 3; s++) {
                uint32_t mb = sbase + PMB_OFF + s * 8;
                MBAR_EXPECT(mb, HCH_SZ);
                cp_bulk(sbase + HB_OFF + (uint32_t)s * HCH_SZ, hsrc + (size_t)s * HCH_SZ, HCH_SZ, mb);
            }
        }

        float C[2][4];
#pragma unroll
        for (int q = 0; q < 4; q++) { C[0][q] = 0.0f; C[1][q] = 0.0f; }

        for (int ch = 0; ch < 16; ch++) {
            MBAR_WAIT(sbase + PMB_OFF + (ch & 3) * 8, (ch >> 2) & 1);
            __syncthreads();
            if (tid == 0 && ch < 13) {
                int nc = ch + 3;
                uint32_t mb = sbase + PMB_OFF + (nc & 3) * 8;
                MBAR_EXPECT(mb, HCH_SZ);
                cp_bulk(sbase + HB_OFF + (uint32_t)(nc & 3) * HCH_SZ, hsrc + (size_t)nc * HCH_SZ, HCH_SZ, mb);
            }

            const uint32_t abuf = sbase + HB_OFF + (uint32_t)(ch & 3) * HCH_SZ + a_lane_off;
            const uint32_t bco = (uint32_t)ch * 128;  // 64 cols * 2B

            uint32_t fa[2][2][4], fb[2][2];
            ldsm_x2(fb[0], b_base + bco);
            ldsm_x4(fa[0][0], abuf);
            ldsm_x4(fa[0][1], abuf + 2304);
#pragma unroll
            for (int k16 = 0; k16 < 4; k16++) {
                int cur = k16 & 1;
                if (k16 < 3) {
                    int nb = cur ^ 1;
                    uint32_t kb = (uint32_t)(k16 + 1) * 32;
                    ldsm_x2(fb[nb], b_base + bco + kb);
                    ldsm_x4(fa[nb][0], abuf + kb);
                    ldsm_x4(fa[nb][1], abuf + 2304 + kb);
                }
                mma_f16(C[0], fa[cur][0], fb[cur]);
                mma_f16(C[1], fa[cur][1], fb[cur]);
            }
        }

        // ---- epilogue ----
        MBAR_WAIT(mb_gx, t & 1);
        float v[2][4], p[2][4];
#pragma unroll
        for (int mt = 0; mt < 2; mt++) {
            int r0 = wm + mt * 16 + g;
            int r1 = r0 + 8;
            int col = wn + 2 * tq;
            v[mt][0] = C[mt][0] + gxs[r0 * 36 + col];
            v[mt][1] = C[mt][1] + gxs[r0 * 36 + col + 1];
            v[mt][2] = C[mt][2] + gxs[r1 * 36 + col];
            v[mt][3] = C[mt][3] + gxs[r1 * 36 + col + 1];
        }
#pragma unroll
        for (int mt = 0; mt < 2; mt++)
#pragma unroll
            for (int q = 0; q < 4; q++)
                p[mt][q] = __shfl_xor_sync(0xffffffffu, v[mt][q], 1);

        float ii0, ff0, cc0, oo0, ii1, ff1, cc1, oo1;
        if (myMt == 0) {
            ii0 = v[0][0]; ff0 = v[0][1]; cc0 = p[0][0]; oo0 = p[0][1];
            ii1 = v[0][2]; ff1 = v[0][3]; cc1 = p[0][2]; oo1 = p[0][3];
        } else {
            ii0 = p[1][0]; ff0 = p[1][1]; cc0 = v[1][0]; oo0 = v[1][1];
            ii1 = p[1][2]; ff1 = p[1][3]; cc1 = v[1][2]; oo1 = v[1][3];
        }

        float cn0 = fmaf(sigf(ff0), creg0, sigf(ii0) * tanhf_fast(cc0));
        float cn1 = fmaf(sigf(ff1), creg1, sigf(ii1) * tanhf_fast(cc1));
        creg0 = cn0; creg1 = cn1;
        float hn0 = sigf(oo0) * tanhf_fast(cn0);
        float hn1 = sigf(oo1) * tanhf_fast(cn1);
        hlast0 = hn0; hlast1 = hn1;

        const int np = (t + 1) & 1;
        __half* hb = &g_hbulk[np][u_ch][0];
        hb[row0 * 72 + u_c] = __float2half(hn0);
        hb[row1 * 72 + u_c] = __float2half(hn1);

        if (t + 1 < Tt) {
            __syncthreads();   // all h stores done block-wide
            if (tid == 0) { __threadfence(); g_flagsv[bu * 32] = t + 1; }
            // hide out-seq stores in the barrier window
            out[(size_t)t * (Bb * Hh) + row0 * Hh + u_glob] = hn0;
            out[(size_t)t * (Bb * Hh) + row1 * Hh + u_glob] = hn1;
            if (tid < NBLK) {
                while (g_flagsv[tid * 32] < t + 1) nsleep();
                __threadfence();
            }
            __syncthreads();
        } else {
            out[(size_t)t * (Bb * Hh) + row0 * Hh + u_glob] = hn0;
            out[(size_t)t * (Bb * Hh) + row1 * Hh + u_glob] = hn1;
        }
    }

    // final h_T, c_T
    size_t base = (size_t)Tt * Bb * Hh;
    out[base + row0 * Hh + u_glob] = hlast0;
    out[base + row1 * Hh + u_glob] = hlast1;
    out[base + Bb * Hh + row0 * Hh + u_glob] = creg0;
    out[base + Bb * Hh + row1 * Hh + u_glob] = creg1;
}

// ---------------------------------------------------------------------------
extern "C" void kernel_launch(void* const* d_in, const int* in_sizes, int n_in,
                              void* d_out, int out_size) {
    const float* x  = (const float*)d_in[0];
    const float* Wi = (const float*)d_in[1];
    const float* bi = (const float*)d_in[2];
    const float* Wf = (const float*)d_in[3];
    const float* bf = (const float*)d_in[4];
    const float* Wc = (const float*)d_in[5];
    const float* bc = (const float*)d_in[6];
    const float* Wo = (const float*)d_in[7];
    const float* bo = (const float*)d_in[8];
    float* out = (float*)d_out;

    cudaFuncSetAttribute(gemm_x_mma, cudaFuncAttributeMaxDynamicSharedMemorySize, GX_SMEM);
    cudaFuncSetAttribute(lstm_persist, cudaFuncAttributeMaxDynamicSharedMemorySize, PERSIST_SMEM);

    repack_kernel<<<512, 256>>>(Wi, Wf, Wc, Wo, bi, bf, bc, bo);
    split_x_kernel<<<1024, 256>>>(x);
    init_state_kernel<<<512, 256>>>();

    gemm_x_mma<<<dim3(G4 / 128, (Tt * Bb) / 128), 256, GX_SMEM>>>();

    lstm_persist<<<NBLK, 256, PERSIST_SMEM>>>(out);
}

// round 10
// speedup vs baseline: 2.1689x; 1.1323x over previous
#include <cuda_runtime.h>
#include <cuda_fp16.h>
#include <cstdint>
#include <math.h>

#define Tt 512
#define Bb 64
#define Hh 1024
#define G4 4096
#define K2 2048
#define NBLK 128

// ---------------------------------------------------------------------------
// Device globals. Weight rows UNIT-MAJOR: j = u*4 + g, g in {i,f,c,o}.
// Chunk-major fp16 layouts; staging is pure cp.async.bulk byte copies.
// ---------------------------------------------------------------------------
__device__ __align__(128) __half g_xc[(size_t)256 * 32 * 5120];
__device__ __align__(128) __half g_wc[(size_t)32 * 32 * 5120];
__device__ __align__(128) __half g_Wh[(size_t)G4 * Hh];
__device__ float g_bias[G4];
// gx: [t=512][blk=128][64 rows * 36 cols] f32 (9216 B per (t,blk))
__device__ __align__(128) float g_gx2[(size_t)Tt * NBLK * 2304];
// h: [parity][ch=16][64 rows * 72 stride] fp16 (9216 B per chunk)
__device__ __align__(128) __half g_hbulk[2][16][4608];
// per-chunk producer arrival counters (padded to separate L2 lines)
__device__ volatile int g_ctr16[16 * 32];

// ---------------------------------------------------------------------------
// PTX helpers — non-'a' instructions only
// ---------------------------------------------------------------------------
__device__ __forceinline__ uint32_t smem_u32(const void* p) {
    uint32_t a;
    asm("{ .reg .u64 t; cvta.to.shared.u64 t, %1; cvt.u32.u64 %0, t; }" : "=r"(a) : "l"(p));
    return a;
}
__device__ __forceinline__ void cp16(uint32_t dst, const void* src) {
    asm volatile("cp.async.cg.shared.global [%0], [%1], 16;" :: "r"(dst), "l"(src) : "memory");
}
#define CP_COMMIT() asm volatile("cp.async.commit_group;" ::: "memory")
template <int N>
__device__ __forceinline__ void cp_wait() {
    asm volatile("cp.async.wait_group %0;" :: "n"(N) : "memory");
}
__device__ __forceinline__ void cp_bulk(uint32_t dst, const void* src, uint32_t bytes, uint32_t mbar) {
    asm volatile("cp.async.bulk.shared::cluster.global.mbarrier::complete_tx::bytes [%0], [%1], %2, [%3];"
                 :: "r"(dst), "l"(src), "r"(bytes), "r"(mbar) : "memory");
}
#define MBAR_INIT(mb, c)  asm volatile("mbarrier.init.shared.b64 [%0], %1;" :: "r"((uint32_t)(mb)), "r"((uint32_t)(c)) : "memory")
#define MBAR_EXPECT(mb, b) asm volatile("mbarrier.arrive.expect_tx.shared.b64 _, [%0], %1;" :: "r"((uint32_t)(mb)), "r"((uint32_t)(b)) : "memory")
#define MBAR_WAIT(mb, ph) do { \
    uint32_t _m = (uint32_t)(mb), _p = (uint32_t)(ph), _d; \
    asm volatile("{\n\t.reg .pred p;\n\tmbarrier.try_wait.parity.acquire.cta.shared::cta.b64 p, [%1], %2;\n\tselp.b32 %0, 1, 0, p;\n\t}" \
        : "=r"(_d) : "r"(_m), "r"(_p) : "memory"); \
    if (!_d) { \
        asm volatile("{\n\t.reg .pred P1;\n\tWL_%=: mbarrier.try_wait.parity.acquire.cta.shared::cta.b64 P1, [%0], %1, 0x989680;\n\t@P1 bra.uni WD_%=;\n\tbra.uni WL_%=;\n\tWD_%=:\n\t}" \
            :: "r"(_m), "r"(_p) : "memory"); \
    } \
} while (0)

__device__ __forceinline__ void mma_f16(float* c, const uint32_t* a, const uint32_t* b) {
    asm volatile(
        "mma.sync.aligned.m16n8k16.row.col.f32.f16.f16.f32 "
        "{%0,%1,%2,%3}, {%4,%5,%6,%7}, {%8,%9}, {%0,%1,%2,%3};"
        : "+f"(c[0]), "+f"(c[1]), "+f"(c[2]), "+f"(c[3])
        : "r"(a[0]), "r"(a[1]), "r"(a[2]), "r"(a[3]), "r"(b[0]), "r"(b[1]));
}
__device__ __forceinline__ void mma_f16b(float* c, const uint32_t* a, uint32_t b0, uint32_t b1) {
    asm volatile(
        "mma.sync.aligned.m16n8k16.row.col.f32.f16.f16.f32 "
        "{%0,%1,%2,%3}, {%4,%5,%6,%7}, {%8,%9}, {%0,%1,%2,%3};"
        : "+f"(c[0]), "+f"(c[1]), "+f"(c[2]), "+f"(c[3])
        : "r"(a[0]), "r"(a[1]), "r"(a[2]), "r"(a[3]), "r"(b0), "r"(b1));
}
__device__ __forceinline__ void ldsm_x4(uint32_t* r, uint32_t addr) {
    asm volatile("ldmatrix.sync.aligned.m8n8.x4.shared.b16 {%0,%1,%2,%3}, [%4];"
                 : "=r"(r[0]), "=r"(r[1]), "=r"(r[2]), "=r"(r[3]) : "r"(addr));
}
__device__ __forceinline__ void ldsm_x2(uint32_t* r, uint32_t addr) {
    asm volatile("ldmatrix.sync.aligned.m8n8.x2.shared.b16 {%0,%1}, [%2];"
                 : "=r"(r[0]), "=r"(r[1]) : "r"(addr));
}
__device__ __forceinline__ void nsleep() { asm volatile("nanosleep.u32 40;"); }

__device__ __forceinline__ float sigf(float v) { return 1.0f / (1.0f + __expf(-v)); }
__device__ __forceinline__ float tanhf_fast(float v) {
    float e = __expf(-2.0f * fabsf(v));
    float r = (1.0f - e) / (1.0f + e);
    return (v >= 0.0f) ? r : -r;
}

// ---------------------------------------------------------------------------
// Prep kernels
// ---------------------------------------------------------------------------
__global__ void split_x_kernel(const float* __restrict__ x) {
    size_t total = (size_t)Tt * Bb * Hh;
    size_t stride = (size_t)gridDim.x * blockDim.x;
    for (size_t i = (size_t)blockIdx.x * blockDim.x + threadIdx.x; i < total; i += stride) {
        float v = x[i];
        size_t m = i >> 10;
        int k = (int)(i & 1023);
        size_t dst = ((m >> 7) * 32 + (k >> 5)) * 5120 + (m & 127) * 40 + (k & 31);
        g_xc[dst] = __float2half(v);
    }
}

__global__ void repack_kernel(const float* __restrict__ Wi, const float* __restrict__ Wf,
                              const float* __restrict__ Wc, const float* __restrict__ Wo,
                              const float* __restrict__ bi, const float* __restrict__ bf,
                              const float* __restrict__ bc, const float* __restrict__ bo) {
    size_t total = (size_t)G4 * K2;
    size_t stride = (size_t)gridDim.x * blockDim.x;
    for (size_t idx = (size_t)blockIdx.x * blockDim.x + threadIdx.x; idx < total; idx += stride) {
        int j = (int)(idx / K2);
        int k = (int)(idx % K2);
        int u = j >> 2, g = j & 3;
        const float* src = (g == 0) ? Wi : (g == 1) ? Wf : (g == 2) ? Wc : Wo;
        float v = src[(size_t)u * K2 + k];
        if (k < Hh) {
            size_t dst = ((size_t)(j >> 7) * 32 + (k >> 5)) * 5120 + (j & 127) * 40 + (k & 31);
            g_wc[dst] = __float2half(v);
        } else {
            g_Wh[(size_t)j * Hh + (k - Hh)] = __float2half(v);
        }
    }
    for (int j = blockIdx.x * blockDim.x + threadIdx.x; j < G4; j += (int)stride) {
        int u = j >> 2, g = j & 3;
        const float* sb = (g == 0) ? bi : (g == 1) ? bf : (g == 2) ? bc : bo;
        g_bias[j] = sb[u];
    }
}

__global__ void init_state_kernel() {
    int i = blockIdx.x * blockDim.x + threadIdx.x;
    int stride = gridDim.x * blockDim.x;
    __half z = __float2half(0.0f);
    for (int k = i; k < 16 * 4608; k += stride) {
        g_hbulk[0][k / 4608][k % 4608] = z;
    }
    for (int k = i; k < 16 * 32; k += stride) g_ctr16[k] = 0;
}

// ---------------------------------------------------------------------------
// x-GEMM: gx = x @ Wx^T + b, fp16 single-product via mma.sync.
// CTA 128x128, 8 warps, warp tile 64x32. K chunks of 32, 4-slot bulk ring,
// 2 CTAs/SM.
// ---------------------------------------------------------------------------
#define RS 40
#define ARR (128 * RS * 2)              // 10240 B
#define SLOT (2 * ARR)                  // A + B
#define GX_MB (4 * SLOT)                // 81920
#define GX_SMEM (GX_MB + 32)

__global__ __launch_bounds__(256, 2) void gemm_x_mma() {
    extern __shared__ char smem[];
    const uint32_t sbase = smem_u32(smem);
    const int tid = threadIdx.x;
    const int w = tid >> 5;
    const int lane = tid & 31;
    const int g = lane >> 2;
    const int t = lane & 3;
    const int nblk = blockIdx.x;
    const int mblk = blockIdx.y;
    const int n0 = nblk * 128;
    const int m0 = mblk * 128;
    const int wm = (w >> 2) * 64;
    const int wn = (w & 3) * 32;
    const int lrow = (lane & 7) + ((lane >> 3) & 1) * 8;
    const int lcol = (lane >> 4) * 8;

    if (tid == 0) {
#pragma unroll
        for (int s = 0; s < 4; s++) MBAR_INIT(sbase + GX_MB + s * 8, 1);
    }
    __syncthreads();

    auto stage = [&](int ch) {
        uint32_t base = sbase + (uint32_t)(ch & 3) * SLOT;
        uint32_t mb = sbase + GX_MB + (ch & 3) * 8;
        MBAR_EXPECT(mb, SLOT);
        cp_bulk(base, g_xc + ((size_t)mblk * 32 + ch) * 5120, ARR, mb);
        cp_bulk(base + ARR, g_wc + ((size_t)nblk * 32 + ch) * 5120, ARR, mb);
    };

    float C[4][4][4];
#pragma unroll
    for (int i = 0; i < 4; i++)
#pragma unroll
        for (int j = 0; j < 4; j++)
#pragma unroll
            for (int q = 0; q < 4; q++) C[i][j][q] = 0.0f;

    const uint32_t a_off = (uint32_t)((wm + lrow) * RS + lcol) * 2;
    const uint32_t b_off = (uint32_t)((wn + lrow) * RS + lcol) * 2;

    if (tid == 0) { stage(0); stage(1); stage(2); }
    for (int ch = 0; ch < 32; ch++) {
        MBAR_WAIT(sbase + GX_MB + (ch & 3) * 8, (ch >> 2) & 1);
        __syncthreads();
        if (tid == 0 && ch < 29) stage(ch + 3);
        const uint32_t buf = sbase + (uint32_t)(ch & 3) * SLOT;
#pragma unroll
        for (int kk = 0; kk < 32; kk += 16) {
            uint32_t ah[4][4], bh[2][4];
#pragma unroll
            for (int mt = 0; mt < 4; mt++)
                ldsm_x4(ah[mt], buf + a_off + (uint32_t)(mt * 16 * RS + kk) * 2);
#pragma unroll
            for (int p = 0; p < 2; p++)
                ldsm_x4(bh[p], buf + ARR + b_off + (uint32_t)(p * 16 * RS + kk) * 2);
#pragma unroll
            for (int mt = 0; mt < 4; mt++)
#pragma unroll
                for (int nt = 0; nt < 4; nt++) {
                    int p = nt >> 1, s = nt & 1;
                    mma_f16b(C[mt][nt], ah[mt], bh[p][s], bh[p][s + 2]);
                }
        }
    }

    // Epilogue: add bias, store into chunk-major gx2
#pragma unroll
    for (int mt = 0; mt < 4; mt++) {
        int row = m0 + wm + mt * 16 + g;
        int t_idx = row >> 6;
        int batch = row & 63;
#pragma unroll
        for (int nt = 0; nt < 4; nt++) {
            int col = n0 + wn + nt * 8 + 2 * t;
            int buI = col >> 5;
            int cs = col & 31;
            float2 bv = *reinterpret_cast<const float2*>(g_bias + col);
            float2 o0 = { C[mt][nt][0] + bv.x, C[mt][nt][1] + bv.y };
            float2 o1 = { C[mt][nt][2] + bv.x, C[mt][nt][3] + bv.y };
            float* dst = g_gx2 + ((size_t)t_idx * NBLK + buI) * 2304;
            *reinterpret_cast<float2*>(dst + batch * 36 + cs) = o0;
            *reinterpret_cast<float2*>(dst + (batch + 8) * 36 + cs) = o1;
        }
    }
}

// ---------------------------------------------------------------------------
// Persistent recurrent kernel: 128 blocks x 256 threads, all 512 steps.
// Barrier-free dataflow: 16 per-chunk producer counters; 16 dedicated smem
// slots staged by 16 poller threads (one per chunk, spread across warps).
// SMEM (bytes):
//   WH [32][1032] fp16 @ 0          (66048)
//   H slots: 16 x 9216 @ 66048      (147456)
//   GXS [64][36] f32 @ 213504       (9216)
//   mbarriers @ 222720 (17 x 8)     -> total 222856
// ---------------------------------------------------------------------------
#define WH_OFF 0
#define HB_OFF 66048
#define HCH_SZ 9216
#define GXS_OFF 213504
#define PMB_OFF 222720
#define PERSIST_SMEM 222856

__global__ __launch_bounds__(256, 1) void lstm_persist(float* __restrict__ out) {
    extern __shared__ char smem[];
    const uint32_t sbase = smem_u32(smem);
    const int tid = threadIdx.x;
    const int bu = blockIdx.x;
    const int w = tid >> 5;
    const int lane = tid & 31;
    const int g = lane >> 2;
    const int tq = lane & 3;
    const int wm = (w >> 2) * 32;   // 0 or 32
    const int wn = (w & 3) * 8;     // 0,8,16,24

    if (tid == 0) {
#pragma unroll
        for (int s = 0; s < 17; s++) MBAR_INIT(sbase + PMB_OFF + s * 8, 1);
    }

    // ---- load Wh slice into smem (once) ----
    {
        const __half* ws = g_Wh + (size_t)bu * 32 * Hh;
#pragma unroll
        for (int q = 0; q < 16; q++) {
            int idx = q * 256 + tid;
            int row = idx >> 7;
            int seg = idx & 127;
            cp16(sbase + WH_OFF + (uint32_t)(row * 1032 + seg * 8) * 2,
                 ws + (size_t)row * Hh + seg * 8);
        }
        CP_COMMIT();
        cp_wait<0>();
    }
    __syncthreads();

    const int lrow = (lane & 7) + ((lane >> 3) & 1) * 8;
    const int lcol = (lane >> 4) * 8;
    const uint32_t a_lane_off = (uint32_t)((wm + lrow) * 72 + lcol) * 2;
    const uint32_t b_lane_off = (uint32_t)((wn + (lane & 7)) * 1032 + ((lane >> 3) & 1) * 8) * 2;
    const uint32_t b_base = sbase + WH_OFF + b_lane_off;

    const int myMt = tq & 1;
    const int row0 = wm + myMt * 16 + g;
    const int row1 = row0 + 8;
    const int u_glob = bu * 8 + (wn >> 2) + (tq >> 1);
    const int u_ch = u_glob >> 6;       // == bu >> 3
    const int u_c = u_glob & 63;
    const int chunk0 = bu >> 3;         // start at own chunk (skew-friendly)

    const bool is_poller = ((tid & 15) == 0);
    const int pch = tid >> 4;           // 0..15, spread across warps

    float creg0 = 0.0f, creg1 = 0.0f;
    float hlast0 = 0.0f, hlast1 = 0.0f;
    const float* gxs = reinterpret_cast<const float*>(smem + GXS_OFF);
    const uint32_t mb_gx = sbase + PMB_OFF + 16 * 8;

    for (int t = 0; t < Tt; t++) {
        const int par = t & 1;
        const char* hsrc = reinterpret_cast<const char*>(&g_hbulk[par][0][0]);

        // ---- staging: 16 pollers, one chunk each; tid 1 stages gx ----
        if (is_poller) {
            int need = 8 * t;
            while (g_ctr16[pch * 32] < need) nsleep();
            __threadfence();  // acquire vs producer stores
            uint32_t mb = sbase + PMB_OFF + pch * 8;
            MBAR_EXPECT(mb, HCH_SZ);
            cp_bulk(sbase + HB_OFF + (uint32_t)pch * HCH_SZ,
                    hsrc + (size_t)pch * HCH_SZ, HCH_SZ, mb);
        }
        if (tid == 1) {
            MBAR_EXPECT(mb_gx, 9216);
            cp_bulk(sbase + GXS_OFF, g_gx2 + ((size_t)t * NBLK + bu) * 2304, 9216, mb_gx);
        }

        float C[2][4];
#pragma unroll
        for (int q = 0; q < 4; q++) { C[0][q] = 0.0f; C[1][q] = 0.0f; }

        for (int i = 0; i < 16; i++) {
            const int ch = (i + chunk0) & 15;
            MBAR_WAIT(sbase + PMB_OFF + ch * 8, t & 1);

            const uint32_t abuf = sbase + HB_OFF + (uint32_t)ch * HCH_SZ + a_lane_off;
            const uint32_t bco = (uint32_t)ch * 128;  // 64 cols * 2B

            uint32_t fa[2][2][4], fb[2][2];
            ldsm_x2(fb[0], b_base + bco);
            ldsm_x4(fa[0][0], abuf);
            ldsm_x4(fa[0][1], abuf + 2304);
#pragma unroll
            for (int k16 = 0; k16 < 4; k16++) {
                int cur = k16 & 1;
                if (k16 < 3) {
                    int nb = cur ^ 1;
                    uint32_t kb = (uint32_t)(k16 + 1) * 32;
                    ldsm_x2(fb[nb], b_base + bco + kb);
                    ldsm_x4(fa[nb][0], abuf + kb);
                    ldsm_x4(fa[nb][1], abuf + 2304 + kb);
                }
                mma_f16(C[0], fa[cur][0], fb[cur]);
                mma_f16(C[1], fa[cur][1], fb[cur]);
            }
        }

        // ---- epilogue ----
        MBAR_WAIT(mb_gx, t & 1);
        float v[2][4], p[2][4];
#pragma unroll
        for (int mt = 0; mt < 2; mt++) {
            int r0 = wm + mt * 16 + g;
            int r1 = r0 + 8;
            int col = wn + 2 * tq;
            v[mt][0] = C[mt][0] + gxs[r0 * 36 + col];
            v[mt][1] = C[mt][1] + gxs[r0 * 36 + col + 1];
            v[mt][2] = C[mt][2] + gxs[r1 * 36 + col];
            v[mt][3] = C[mt][3] + gxs[r1 * 36 + col + 1];
        }
#pragma unroll
        for (int mt = 0; mt < 2; mt++)
#pragma unroll
            for (int q = 0; q < 4; q++)
                p[mt][q] = __shfl_xor_sync(0xffffffffu, v[mt][q], 1);

        float ii0, ff0, cc0, oo0, ii1, ff1, cc1, oo1;
        if (myMt == 0) {
            ii0 = v[0][0]; ff0 = v[0][1]; cc0 = p[0][0]; oo0 = p[0][1];
            ii1 = v[0][2]; ff1 = v[0][3]; cc1 = p[0][2]; oo1 = p[0][3];
        } else {
            ii0 = p[1][0]; ff0 = p[1][1]; cc0 = v[1][0]; oo0 = v[1][1];
            ii1 = p[1][2]; ff1 = p[1][3]; cc1 = v[1][2]; oo1 = v[1][3];
        }

        float cn0 = fmaf(sigf(ff0), creg0, sigf(ii0) * tanhf_fast(cc0));
        float cn1 = fmaf(sigf(ff1), creg1, sigf(ii1) * tanhf_fast(cc1));
        creg0 = cn0; creg1 = cn1;
        float hn0 = sigf(oo0) * tanhf_fast(cn0);
        float hn1 = sigf(oo1) * tanhf_fast(cn1);
        hlast0 = hn0; hlast1 = hn1;

        const int np = (t + 1) & 1;
        __half* hb = &g_hbulk[np][u_ch][0];
        hb[row0 * 72 + u_c] = __float2half(hn0);
        hb[row1 * 72 + u_c] = __float2half(hn1);

        // block-wide completion, then producer arrival for our chunk
        __syncthreads();
        if (t + 1 < Tt && tid == 0) {
            __threadfence();
            atomicAdd((int*)&g_ctr16[u_ch * 32], 1);
        }

        out[(size_t)t * (Bb * Hh) + row0 * Hh + u_glob] = hn0;
        out[(size_t)t * (Bb * Hh) + row1 * Hh + u_glob] = hn1;
    }

    // final h_T, c_T
    size_t base = (size_t)Tt * Bb * Hh;
    out[base + row0 * Hh + u_glob] = hlast0;
    out[base + row1 * Hh + u_glob] = hlast1;
    out[base + Bb * Hh + row0 * Hh + u_glob] = creg0;
    out[base + Bb * Hh + row1 * Hh + u_glob] = creg1;
}

// ---------------------------------------------------------------------------
extern "C" void kernel_launch(void* const* d_in, const int* in_sizes, int n_in,
                              void* d_out, int out_size) {
    const float* x  = (const float*)d_in[0];
    const float* Wi = (const float*)d_in[1];
    const float* bi = (const float*)d_in[2];
    const float* Wf = (const float*)d_in[3];
    const float* bf = (const float*)d_in[4];
    const float* Wc = (const float*)d_in[5];
    const float* bc = (const float*)d_in[6];
    const float* Wo = (const float*)d_in[7];
    const float* bo = (const float*)d_in[8];
    float* out = (float*)d_out;

    cudaFuncSetAttribute(gemm_x_mma, cudaFuncAttributeMaxDynamicSharedMemorySize, GX_SMEM);
    cudaFuncSetAttribute(lstm_persist, cudaFuncAttributeMaxDynamicSharedMemorySize, PERSIST_SMEM);

    repack_kernel<<<512, 256>>>(Wi, Wf, Wc, Wo, bi, bf, bc, bo);
    split_x_kernel<<<1024, 256>>>(x);
    init_state_kernel<<<512, 256>>>();

    gemm_x_mma<<<dim3(G4 / 128, (Tt * Bb) / 128), 256, GX_SMEM>>>();

    lstm_persist<<<NBLK, 256, PERSIST_SMEM>>>(out);
}

// round 11
// speedup vs baseline: 2.1899x; 1.0097x over previous
#include <cuda_runtime.h>
#include <cuda_fp16.h>
#include <cstdint>
#include <math.h>

#define Tt 512
#define Bb 64
#define Hh 1024
#define G4 4096
#define K2 2048
#define NBLK 128

// ---------------------------------------------------------------------------
// Device globals. Weight rows UNIT-MAJOR: j = u*4 + g, g in {i,f,c,o}.
// Chunk-major fp16 layouts; staging is pure cp.async.bulk byte copies.
// ---------------------------------------------------------------------------
__device__ __align__(128) __half g_xc[(size_t)256 * 32 * 5120];
__device__ __align__(128) __half g_wc[(size_t)32 * 32 * 5120];
__device__ __align__(128) __half g_Wh[(size_t)G4 * Hh];
__device__ float g_bias[G4];
// gx: [t=512][blk=128][64 rows * 36 cols] f32 (9216 B per (t,blk))
__device__ __align__(128) float g_gx2[(size_t)Tt * NBLK * 2304];
// h: [parity][ch=16][64 rows * 72 stride] fp16 (9216 B per chunk)
__device__ __align__(128) __half g_hbulk[2][16][4608];
// per-chunk producer arrival counters (padded to separate L2 lines)
__device__ volatile int g_ctr16[16 * 32];

// ---------------------------------------------------------------------------
// PTX helpers — non-'a' instructions only
// ---------------------------------------------------------------------------
__device__ __forceinline__ uint32_t smem_u32(const void* p) {
    uint32_t a;
    asm("{ .reg .u64 t; cvta.to.shared.u64 t, %1; cvt.u32.u64 %0, t; }" : "=r"(a) : "l"(p));
    return a;
}
__device__ __forceinline__ void cp16(uint32_t dst, const void* src) {
    asm volatile("cp.async.cg.shared.global [%0], [%1], 16;" :: "r"(dst), "l"(src) : "memory");
}
#define CP_COMMIT() asm volatile("cp.async.commit_group;" ::: "memory")
template <int N>
__device__ __forceinline__ void cp_wait() {
    asm volatile("cp.async.wait_group %0;" :: "n"(N) : "memory");
}
__device__ __forceinline__ void cp_bulk(uint32_t dst, const void* src, uint32_t bytes, uint32_t mbar) {
    asm volatile("cp.async.bulk.shared::cluster.global.mbarrier::complete_tx::bytes [%0], [%1], %2, [%3];"
                 :: "r"(dst), "l"(src), "r"(bytes), "r"(mbar) : "memory");
}
#define MBAR_INIT(mb, c)  asm volatile("mbarrier.init.shared.b64 [%0], %1;" :: "r"((uint32_t)(mb)), "r"((uint32_t)(c)) : "memory")
#define MBAR_EXPECT(mb, b) asm volatile("mbarrier.arrive.expect_tx.shared.b64 _, [%0], %1;" :: "r"((uint32_t)(mb)), "r"((uint32_t)(b)) : "memory")
#define MBAR_WAIT(mb, ph) do { \
    uint32_t _m = (uint32_t)(mb), _p = (uint32_t)(ph), _d; \
    asm volatile("{\n\t.reg .pred p;\n\tmbarrier.try_wait.parity.acquire.cta.shared::cta.b64 p, [%1], %2;\n\tselp.b32 %0, 1, 0, p;\n\t}" \
        : "=r"(_d) : "r"(_m), "r"(_p) : "memory"); \
    if (!_d) { \
        asm volatile("{\n\t.reg .pred P1;\n\tWL_%=: mbarrier.try_wait.parity.acquire.cta.shared::cta.b64 P1, [%0], %1, 0x989680;\n\t@P1 bra.uni WD_%=;\n\tbra.uni WL_%=;\n\tWD_%=:\n\t}" \
            :: "r"(_m), "r"(_p) : "memory"); \
    } \
} while (0)

__device__ __forceinline__ void mma_f16(float* c, const uint32_t* a, const uint32_t* b) {
    asm volatile(
        "mma.sync.aligned.m16n8k16.row.col.f32.f16.f16.f32 "
        "{%0,%1,%2,%3}, {%4,%5,%6,%7}, {%8,%9}, {%0,%1,%2,%3};"
        : "+f"(c[0]), "+f"(c[1]), "+f"(c[2]), "+f"(c[3])
        : "r"(a[0]), "r"(a[1]), "r"(a[2]), "r"(a[3]), "r"(b[0]), "r"(b[1]));
}
__device__ __forceinline__ void mma_f16b(float* c, const uint32_t* a, uint32_t b0, uint32_t b1) {
    asm volatile(
        "mma.sync.aligned.m16n8k16.row.col.f32.f16.f16.f32 "
        "{%0,%1,%2,%3}, {%4,%5,%6,%7}, {%8,%9}, {%0,%1,%2,%3};"
        : "+f"(c[0]), "+f"(c[1]), "+f"(c[2]), "+f"(c[3])
        : "r"(a[0]), "r"(a[1]), "r"(a[2]), "r"(a[3]), "r"(b0), "r"(b1));
}
__device__ __forceinline__ void ldsm_x4(uint32_t* r, uint32_t addr) {
    asm volatile("ldmatrix.sync.aligned.m8n8.x4.shared.b16 {%0,%1,%2,%3}, [%4];"
                 : "=r"(r[0]), "=r"(r[1]), "=r"(r[2]), "=r"(r[3]) : "r"(addr));
}
__device__ __forceinline__ void ldsm_x2(uint32_t* r, uint32_t addr) {
    asm volatile("ldmatrix.sync.aligned.m8n8.x2.shared.b16 {%0,%1}, [%2];"
                 : "=r"(r[0]), "=r"(r[1]) : "r"(addr));
}
__device__ __forceinline__ void nsleep() { asm volatile("nanosleep.u32 40;"); }
#define BAR_COMPUTE() asm volatile("bar.sync 1, 256;" ::: "memory")

__device__ __forceinline__ float sigf(float v) { return 1.0f / (1.0f + __expf(-v)); }
__device__ __forceinline__ float tanhf_fast(float v) {
    float e = __expf(-2.0f * fabsf(v));
    float r = (1.0f - e) / (1.0f + e);
    return (v >= 0.0f) ? r : -r;
}

// ---------------------------------------------------------------------------
// Prep kernels
// ---------------------------------------------------------------------------
__global__ void split_x_kernel(const float* __restrict__ x) {
    size_t total = (size_t)Tt * Bb * Hh;
    size_t stride = (size_t)gridDim.x * blockDim.x;
    for (size_t i = (size_t)blockIdx.x * blockDim.x + threadIdx.x; i < total; i += stride) {
        float v = x[i];
        size_t m = i >> 10;
        int k = (int)(i & 1023);
        size_t dst = ((m >> 7) * 32 + (k >> 5)) * 5120 + (m & 127) * 40 + (k & 31);
        g_xc[dst] = __float2half(v);
    }
}

__global__ void repack_kernel(const float* __restrict__ Wi, const float* __restrict__ Wf,
                              const float* __restrict__ Wc, const float* __restrict__ Wo,
                              const float* __restrict__ bi, const float* __restrict__ bf,
                              const float* __restrict__ bc, const float* __restrict__ bo) {
    size_t total = (size_t)G4 * K2;
    size_t stride = (size_t)gridDim.x * blockDim.x;
    for (size_t idx = (size_t)blockIdx.x * blockDim.x + threadIdx.x; idx < total; idx += stride) {
        int j = (int)(idx / K2);
        int k = (int)(idx % K2);
        int u = j >> 2, g = j & 3;
        const float* src = (g == 0) ? Wi : (g == 1) ? Wf : (g == 2) ? Wc : Wo;
        float v = src[(size_t)u * K2 + k];
        if (k < Hh) {
            size_t dst = ((size_t)(j >> 7) * 32 + (k >> 5)) * 5120 + (j & 127) * 40 + (k & 31);
            g_wc[dst] = __float2half(v);
        } else {
            g_Wh[(size_t)j * Hh + (k - Hh)] = __float2half(v);
        }
    }
    for (int j = blockIdx.x * blockDim.x + threadIdx.x; j < G4; j += (int)stride) {
        int u = j >> 2, g = j & 3;
        const float* sb = (g == 0) ? bi : (g == 1) ? bf : (g == 2) ? bc : bo;
        g_bias[j] = sb[u];
    }
}

__global__ void init_state_kernel() {
    int i = blockIdx.x * blockDim.x + threadIdx.x;
    int stride = gridDim.x * blockDim.x;
    __half z = __float2half(0.0f);
    for (int k = i; k < 16 * 4608; k += stride) {
        g_hbulk[0][k / 4608][k % 4608] = z;
    }
    for (int k = i; k < 16 * 32; k += stride) g_ctr16[k] = 0;
}

// ---------------------------------------------------------------------------
// x-GEMM: gx = x @ Wx^T + b, fp16 single-product via mma.sync.
// CTA 128x128, 8 warps, warp tile 64x32. K chunks of 32, 4-slot bulk ring,
// 2 CTAs/SM. (unchanged from R10)
// ---------------------------------------------------------------------------
#define RS 40
#define ARR (128 * RS * 2)              // 10240 B
#define SLOT (2 * ARR)                  // A + B
#define GX_MB (4 * SLOT)                // 81920
#define GX_SMEM (GX_MB + 32)

__global__ __launch_bounds__(256, 2) void gemm_x_mma() {
    extern __shared__ char smem[];
    const uint32_t sbase = smem_u32(smem);
    const int tid = threadIdx.x;
    const int w = tid >> 5;
    const int lane = tid & 31;
    const int g = lane >> 2;
    const int t = lane & 3;
    const int nblk = blockIdx.x;
    const int mblk = blockIdx.y;
    const int n0 = nblk * 128;
    const int m0 = mblk * 128;
    const int wm = (w >> 2) * 64;
    const int wn = (w & 3) * 32;
    const int lrow = (lane & 7) + ((lane >> 3) & 1) * 8;
    const int lcol = (lane >> 4) * 8;

    if (tid == 0) {
#pragma unroll
        for (int s = 0; s < 4; s++) MBAR_INIT(sbase + GX_MB + s * 8, 1);
    }
    __syncthreads();

    auto stage = [&](int ch) {
        uint32_t base = sbase + (uint32_t)(ch & 3) * SLOT;
        uint32_t mb = sbase + GX_MB + (ch & 3) * 8;
        MBAR_EXPECT(mb, SLOT);
        cp_bulk(base, g_xc + ((size_t)mblk * 32 + ch) * 5120, ARR, mb);
        cp_bulk(base + ARR, g_wc + ((size_t)nblk * 32 + ch) * 5120, ARR, mb);
    };

    float C[4][4][4];
#pragma unroll
    for (int i = 0; i < 4; i++)
#pragma unroll
        for (int j = 0; j < 4; j++)
#pragma unroll
            for (int q = 0; q < 4; q++) C[i][j][q] = 0.0f;

    const uint32_t a_off = (uint32_t)((wm + lrow) * RS + lcol) * 2;
    const uint32_t b_off = (uint32_t)((wn + lrow) * RS + lcol) * 2;

    if (tid == 0) { stage(0); stage(1); stage(2); }
    for (int ch = 0; ch < 32; ch++) {
        MBAR_WAIT(sbase + GX_MB + (ch & 3) * 8, (ch >> 2) & 1);
        __syncthreads();
        if (tid == 0 && ch < 29) stage(ch + 3);
        const uint32_t buf = sbase + (uint32_t)(ch & 3) * SLOT;
#pragma unroll
        for (int kk = 0; kk < 32; kk += 16) {
            uint32_t ah[4][4], bh[2][4];
#pragma unroll
            for (int mt = 0; mt < 4; mt++)
                ldsm_x4(ah[mt], buf + a_off + (uint32_t)(mt * 16 * RS + kk) * 2);
#pragma unroll
            for (int p = 0; p < 2; p++)
                ldsm_x4(bh[p], buf + ARR + b_off + (uint32_t)(p * 16 * RS + kk) * 2);
#pragma unroll
            for (int mt = 0; mt < 4; mt++)
#pragma unroll
                for (int nt = 0; nt < 4; nt++) {
                    int p = nt >> 1, s = nt & 1;
                    mma_f16b(C[mt][nt], ah[mt], bh[p][s], bh[p][s + 2]);
                }
        }
    }

    // Epilogue: add bias, store into chunk-major gx2
#pragma unroll
    for (int mt = 0; mt < 4; mt++) {
        int row = m0 + wm + mt * 16 + g;
        int t_idx = row >> 6;
        int batch = row & 63;
#pragma unroll
        for (int nt = 0; nt < 4; nt++) {
            int col = n0 + wn + nt * 8 + 2 * t;
            int buI = col >> 5;
            int cs = col & 31;
            float2 bv = *reinterpret_cast<const float2*>(g_bias + col);
            float2 o0 = { C[mt][nt][0] + bv.x, C[mt][nt][1] + bv.y };
            float2 o1 = { C[mt][nt][2] + bv.x, C[mt][nt][3] + bv.y };
            float* dst = g_gx2 + ((size_t)t_idx * NBLK + buI) * 2304;
            *reinterpret_cast<float2*>(dst + batch * 36 + cs) = o0;
            *reinterpret_cast<float2*>(dst + (batch + 8) * 36 + cs) = o1;
        }
    }
}

// ---------------------------------------------------------------------------
// Persistent recurrent kernel: 128 blocks x 288 threads (8 compute warps +
// 1 staging warp), all 512 steps. Warp-specialized dataflow:
//   staging lanes 0..15 poll producer counters + local step_done, bulk-stage
//   their chunk; compute warps only MBAR_WAIT -> ldsm/mma.
// SMEM (bytes):
//   WH [32][1032] fp16 @ 0          (66048)
//   H slots: 16 x 9216 @ 66048      (147456)
//   GXS [64][36] f32 @ 213504       (9216)
//   mbarriers @ 222720 (17 x 8), step_done @ 222856 -> total 222864
// ---------------------------------------------------------------------------
#define WH_OFF 0
#define HB_OFF 66048
#define HCH_SZ 9216
#define GXS_OFF 213504
#define PMB_OFF 222720
#define SDONE_OFF 222856
#define PERSIST_SMEM 222864

__global__ __launch_bounds__(288, 1) void lstm_persist(float* __restrict__ out) {
    extern __shared__ char smem[];
    const uint32_t sbase = smem_u32(smem);
    const int tid = threadIdx.x;
    const int bu = blockIdx.x;
    volatile int* sdone = (volatile int*)(smem + SDONE_OFF);

    if (tid == 0) {
#pragma unroll
        for (int s = 0; s < 17; s++) MBAR_INIT(sbase + PMB_OFF + s * 8, 1);
        *sdone = 0;
    }
    __syncthreads();   // only block-wide sync; before divergence

    // ======================= staging warp =======================
    if (tid >= 256) {
        int L = tid - 256;
        if (L < 16) {
            const uint32_t mb = sbase + PMB_OFF + L * 8;
            const uint32_t dst = sbase + HB_OFF + (uint32_t)L * HCH_SZ;
            for (int t = 0; t < Tt; t++) {
                if (t > 0) {
                    while (*sdone < t) nsleep();                  // local slots free
                    while (g_ctr16[L * 32] < 8 * t) nsleep();     // producers arrived
                    __threadfence();
                }
                MBAR_EXPECT(mb, HCH_SZ);
                cp_bulk(dst, (const char*)&g_hbulk[t & 1][0][0] + (size_t)L * HCH_SZ,
                        HCH_SZ, mb);
            }
        }
        return;
    }

    // ======================= compute warps =======================
    const int w = tid >> 5;
    const int lane = tid & 31;
    const int g = lane >> 2;
    const int tq = lane & 3;
    const int wm = (w >> 2) * 32;   // 0 or 32
    const int wn = (w & 3) * 8;     // 0,8,16,24

    // ---- load Wh slice into smem (once) ----
    {
        const __half* ws = g_Wh + (size_t)bu * 32 * Hh;
#pragma unroll
        for (int q = 0; q < 16; q++) {
            int idx = q * 256 + tid;
            int row = idx >> 7;
            int seg = idx & 127;
            cp16(sbase + WH_OFF + (uint32_t)(row * 1032 + seg * 8) * 2,
                 ws + (size_t)row * Hh + seg * 8);
        }
        CP_COMMIT();
        cp_wait<0>();
    }
    BAR_COMPUTE();

    const int lrow = (lane & 7) + ((lane >> 3) & 1) * 8;
    const int lcol = (lane >> 4) * 8;
    const uint32_t a_lane_off = (uint32_t)((wm + lrow) * 72 + lcol) * 2;
    const uint32_t b_lane_off = (uint32_t)((wn + (lane & 7)) * 1032 + ((lane >> 3) & 1) * 8) * 2;
    const uint32_t b_base = sbase + WH_OFF + b_lane_off;

    const int myMt = tq & 1;
    const int row0 = wm + myMt * 16 + g;
    const int row1 = row0 + 8;
    const int u_glob = bu * 8 + (wn >> 2) + (tq >> 1);
    const int u_ch = u_glob >> 6;       // == bu >> 3
    const int u_c = u_glob & 63;
    const int chunk0 = bu >> 3;

    float creg0 = 0.0f, creg1 = 0.0f;
    float hlast0 = 0.0f, hlast1 = 0.0f;
    const float* gxs = reinterpret_cast<const float*>(smem + GXS_OFF);
    const uint32_t mb_gx = sbase + PMB_OFF + 16 * 8;

    for (int t = 0; t < Tt; t++) {
        if (tid == 1) {
            MBAR_EXPECT(mb_gx, 9216);
            cp_bulk(sbase + GXS_OFF, g_gx2 + ((size_t)t * NBLK + bu) * 2304, 9216, mb_gx);
        }

        float C[2][4];
#pragma unroll
        for (int q = 0; q < 4; q++) { C[0][q] = 0.0f; C[1][q] = 0.0f; }

        for (int i = 0; i < 16; i++) {
            const int ch = (i + chunk0) & 15;
            MBAR_WAIT(sbase + PMB_OFF + ch * 8, t & 1);

            const uint32_t abuf = sbase + HB_OFF + (uint32_t)ch * HCH_SZ + a_lane_off;
            const uint32_t bco = (uint32_t)ch * 128;  // 64 cols * 2B

            uint32_t fa[2][2][4], fb[2][2];
            ldsm_x2(fb[0], b_base + bco);
            ldsm_x4(fa[0][0], abuf);
            ldsm_x4(fa[0][1], abuf + 2304);
#pragma unroll
            for (int k16 = 0; k16 < 4; k16++) {
                int cur = k16 & 1;
                if (k16 < 3) {
                    int nb = cur ^ 1;
                    uint32_t kb = (uint32_t)(k16 + 1) * 32;
                    ldsm_x2(fb[nb], b_base + bco + kb);
                    ldsm_x4(fa[nb][0], abuf + kb);
                    ldsm_x4(fa[nb][1], abuf + 2304 + kb);
                }
                mma_f16(C[0], fa[cur][0], fb[cur]);
                mma_f16(C[1], fa[cur][1], fb[cur]);
            }
        }

        // ---- epilogue ----
        MBAR_WAIT(mb_gx, t & 1);
        float v[2][4], p[2][4];
#pragma unroll
        for (int mt = 0; mt < 2; mt++) {
            int r0 = wm + mt * 16 + g;
            int r1 = r0 + 8;
            int col = wn + 2 * tq;
            v[mt][0] = C[mt][0] + gxs[r0 * 36 + col];
            v[mt][1] = C[mt][1] + gxs[r0 * 36 + col + 1];
            v[mt][2] = C[mt][2] + gxs[r1 * 36 + col];
            v[mt][3] = C[mt][3] + gxs[r1 * 36 + col + 1];
        }
#pragma unroll
        for (int mt = 0; mt < 2; mt++)
#pragma unroll
            for (int q = 0; q < 4; q++)
                p[mt][q] = __shfl_xor_sync(0xffffffffu, v[mt][q], 1);

        float ii0, ff0, cc0, oo0, ii1, ff1, cc1, oo1;
        if (myMt == 0) {
            ii0 = v[0][0]; ff0 = v[0][1]; cc0 = p[0][0]; oo0 = p[0][1];
            ii1 = v[0][2]; ff1 = v[0][3]; cc1 = p[0][2]; oo1 = p[0][3];
        } else {
            ii0 = p[1][0]; ff0 = p[1][1]; cc0 = v[1][0]; oo0 = v[1][1];
            ii1 = p[1][2]; ff1 = p[1][3]; cc1 = v[1][2]; oo1 = v[1][3];
        }

        float cn0 = fmaf(sigf(ff0), creg0, sigf(ii0) * tanhf_fast(cc0));
        float cn1 = fmaf(sigf(ff1), creg1, sigf(ii1) * tanhf_fast(cc1));
        creg0 = cn0; creg1 = cn1;
        float hn0 = sigf(oo0) * tanhf_fast(cn0);
        float hn1 = sigf(oo1) * tanhf_fast(cn1);
        hlast0 = hn0; hlast1 = hn1;

        const int np = (t + 1) & 1;
        __half* hb = &g_hbulk[np][u_ch][0];
        hb[row0 * 72 + u_c] = __float2half(hn0);
        hb[row1 * 72 + u_c] = __float2half(hn1);

        // compute-warp barrier: all h stores done + all slot reads done
        BAR_COMPUTE();
        if (tid == 0) {
            __threadfence();
            atomicAdd((int*)&g_ctr16[u_ch * 32], 1);   // producer arrival
            *sdone = t + 1;                             // local slots free
        }

        out[(size_t)t * (Bb * Hh) + row0 * Hh + u_glob] = hn0;
        out[(size_t)t * (Bb * Hh) + row1 * Hh + u_glob] = hn1;
    }

    // final h_T, c_T
    size_t base = (size_t)Tt * Bb * Hh;
    out[base + row0 * Hh + u_glob] = hlast0;
    out[base + row1 * Hh + u_glob] = hlast1;
    out[base + Bb * Hh + row0 * Hh + u_glob] = creg0;
    out[base + Bb * Hh + row1 * Hh + u_glob] = creg1;
}

// ---------------------------------------------------------------------------
extern "C" void kernel_launch(void* const* d_in, const int* in_sizes, int n_in,
                              void* d_out, int out_size) {
    const float* x  = (const float*)d_in[0];
    const float* Wi = (const float*)d_in[1];
    const float* bi = (const float*)d_in[2];
    const float* Wf = (const float*)d_in[3];
    const float* bf = (const float*)d_in[4];
    const float* Wc = (const float*)d_in[5];
    const float* bc = (const float*)d_in[6];
    const float* Wo = (const float*)d_in[7];
    const float* bo = (const float*)d_in[8];
    float* out = (float*)d_out;

    cudaFuncSetAttribute(gemm_x_mma, cudaFuncAttributeMaxDynamicSharedMemorySize, GX_SMEM);
    cudaFuncSetAttribute(lstm_persist, cudaFuncAttributeMaxDynamicSharedMemorySize, PERSIST_SMEM);

    repack_kernel<<<512, 256>>>(Wi, Wf, Wc, Wo, bi, bf, bc, bo);
    split_x_kernel<<<1024, 256>>>(x);
    init_state_kernel<<<512, 256>>>();

    gemm_x_mma<<<dim3(G4 / 128, (Tt * Bb) / 128), 256, GX_SMEM>>>();

    lstm_persist<<<NBLK, 288, PERSIST_SMEM>>>(out);
}